// round 2
// baseline (speedup 1.0000x reference)
#include <cuda_runtime.h>
#include <cstdint>

#define BATCH 4096
#define SDIM  64
#define OUTD  12
#define BM    128   // batch rows per block
#define BK    16    // K tile

// Scratch ping-pong buffers (max layer width 256)
__device__ float g_buf0[BATCH * 256];
__device__ float g_buf1[BATCH * 256];

__device__ __forceinline__ float liquid_act(float v) {
    return tanhf(v) + 0.1f * sinf(0.5f * v) * cosf(0.3f * v);
}

// Fused: pre[b,n] = sum_s act( (x @ Wi[n])[b,s] + bi[n,s] + bl[n,s] ) * Wo[n,s] + bo[n]
// Block: BM=128 batch rows x one neuron n (S=64 cols). 256 threads.
// Thread tile: 4 rows x 8 cols (4 f32x2 pairs). tm = tid/8 (0..31), tc = tid%8.
__global__ __launch_bounds__(256)
void liquid_gemm_kernel(const float* __restrict__ x,    // [B,K]
                        const float* __restrict__ Wi,   // [N,K,S]
                        const float* __restrict__ bi,   // [N,S]
                        const float* __restrict__ bl,   // [N,S]
                        const float* __restrict__ Wo,   // [N,S]
                        const float* __restrict__ bo,   // [N]
                        float* __restrict__ pre,        // [B,N]
                        int K, int N)
{
    const int n   = blockIdx.y;
    const int b0  = blockIdx.x * BM;
    const int tid = threadIdx.x;
    const int tm  = tid >> 3;   // 0..31  -> rows 4*tm..4*tm+3
    const int tc  = tid & 7;    // 0..7   -> cols 8*tc..8*tc+7

    __shared__ __align__(16) float xs[BK][132];  // k-major, padded (132*4 % 16 == 0)
    __shared__ __align__(16) float ws[BK][66];   // padded   (66*4 % 8 == 0)

    unsigned long long acc[4][4];
    #pragma unroll
    for (int i = 0; i < 4; ++i)
        #pragma unroll
        for (int p = 0; p < 4; ++p) acc[i][p] = 0ull;

    const float* WiN = Wi + (size_t)n * K * SDIM;

    for (int k0 = 0; k0 < K; k0 += BK) {
        // Load X tile transposed: xs[k][r] = x[b0+r][k0+k]
        #pragma unroll
        for (int i = 0; i < (BM * BK) / 256; ++i) {
            int idx = tid + i * 256;
            int r = idx >> 4;
            int k = idx & 15;
            xs[k][r] = x[(size_t)(b0 + r) * K + (k0 + k)];
        }
        // Load Wi tile: ws[k][s] = Wi[n][k0+k][s]  (contiguous)
        #pragma unroll
        for (int i = 0; i < (BK * SDIM) / 256; ++i) {
            int idx = tid + i * 256;
            int k = idx >> 6;
            int s = idx & 63;
            ws[k][s] = WiN[(size_t)(k0 + k) * SDIM + s];
        }
        __syncthreads();

        #pragma unroll
        for (int k = 0; k < BK; ++k) {
            float4 a4 = *reinterpret_cast<const float4*>(&xs[k][4 * tm]);
            unsigned long long b2[4];
            #pragma unroll
            for (int p = 0; p < 4; ++p)
                b2[p] = *reinterpret_cast<const unsigned long long*>(&ws[k][8 * tc + 2 * p]);
            float av[4] = {a4.x, a4.y, a4.z, a4.w};
            #pragma unroll
            for (int i = 0; i < 4; ++i) {
                unsigned long long ap;
                asm("mov.b64 %0, {%1, %1};" : "=l"(ap) : "r"(__float_as_uint(av[i])));
                #pragma unroll
                for (int p = 0; p < 4; ++p)
                    asm("fma.rn.f32x2 %0, %1, %2, %0;" : "+l"(acc[i][p]) : "l"(ap), "l"(b2[p]));
            }
        }
        __syncthreads();
    }

    // Epilogue: +bias, activation, dot with Wo over s, reduce across tc lanes
    const float* biN = bi + (size_t)n * SDIM;
    const float* blN = bl + (size_t)n * SDIM;
    const float* WoN = Wo + (size_t)n * SDIM;

    float psum[4] = {0.f, 0.f, 0.f, 0.f};
    #pragma unroll
    for (int p = 0; p < 4; ++p) {
        int s = 8 * tc + 2 * p;
        float b0s = biN[s] + blN[s];
        float b1s = biN[s + 1] + blN[s + 1];
        float w0 = WoN[s], w1 = WoN[s + 1];
        #pragma unroll
        for (int i = 0; i < 4; ++i) {
            float v0 = __uint_as_float((unsigned)(acc[i][p] & 0xffffffffull)) + b0s;
            float v1 = __uint_as_float((unsigned)(acc[i][p] >> 32)) + b1s;
            psum[i] += liquid_act(v0) * w0 + liquid_act(v1) * w1;
        }
    }
    // reduce over the 8 tc lanes (contiguous lane segments of 8)
    #pragma unroll
    for (int off = 4; off > 0; off >>= 1)
        #pragma unroll
        for (int i = 0; i < 4; ++i)
            psum[i] += __shfl_down_sync(0xffffffffu, psum[i], off, 8);

    if (tc == 0) {
        float bon = bo[n];
        #pragma unroll
        for (int i = 0; i < 4; ++i) {
            int r = 4 * tm + i;
            pre[(size_t)(b0 + r) * N + n] = psum[i] + bon;
        }
    }
}

// h[b,n] = (pre[b,n] + 0.1 * sum_m pre[b,m] * L[m,n]) * a[n]
__global__ __launch_bounds__(256)
void lateral_kernel(const float* __restrict__ pre, const float* __restrict__ L,
                    const float* __restrict__ a, float* __restrict__ h, int N)
{
    const int b0  = blockIdx.x * 16;
    const int tid = threadIdx.x;
    __shared__ float ps[16 * 256];

    for (int idx = tid; idx < 16 * N; idx += 256)
        ps[idx] = pre[(size_t)(b0 + idx / N) * N + (idx % N)];
    __syncthreads();

    for (int idx = tid; idx < 16 * N; idx += 256) {
        int r = idx / N;
        int n = idx - r * N;
        const float* pr = ps + r * N;
        float sum = 0.f;
        #pragma unroll 4
        for (int m = 0; m < N; ++m)
            sum += pr[m] * L[(size_t)m * N + n];
        h[(size_t)(b0 + r) * N + n] = (pr[n] + 0.1f * sum) * a[n];
    }
}

// y[b,o] = h[b,:] @ Wout + bout
__global__ __launch_bounds__(256)
void out_kernel(const float* __restrict__ h, const float* __restrict__ Wout,
                const float* __restrict__ bout, float* __restrict__ y)
{
    int idx = blockIdx.x * blockDim.x + threadIdx.x;
    if (idx >= BATCH * OUTD) return;
    int b = idx / OUTD;
    int o = idx - b * OUTD;
    const float* hb = h + (size_t)b * 64;
    float s = bout[o];
    #pragma unroll
    for (int m = 0; m < 64; ++m)
        s += hb[m] * Wout[m * OUTD + o];
    y[idx] = s;
}

extern "C" void kernel_launch(void* const* d_in, const int* in_sizes, int n_in,
                              void* d_out, int out_size)
{
    (void)in_sizes; (void)n_in; (void)out_size;
    const float* x    = (const float*)d_in[0];
    // layer l params at base = 1 + 7*l : Wi, bi, bl, Wo, bo, L, a
    const float* Wi[3]; const float* bi[3]; const float* bl[3];
    const float* Wo[3]; const float* bo[3]; const float* Lm[3]; const float* ad[3];
    for (int l = 0; l < 3; ++l) {
        int base = 1 + 7 * l;
        Wi[l] = (const float*)d_in[base + 0];
        bi[l] = (const float*)d_in[base + 1];
        bl[l] = (const float*)d_in[base + 2];
        Wo[l] = (const float*)d_in[base + 3];
        bo[l] = (const float*)d_in[base + 4];
        Lm[l] = (const float*)d_in[base + 5];
        ad[l] = (const float*)d_in[base + 6];
    }
    const float* Wout = (const float*)d_in[22];
    const float* bout = (const float*)d_in[23];

    float* buf0 = nullptr; float* buf1 = nullptr;
    cudaGetSymbolAddress((void**)&buf0, g_buf0);
    cudaGetSymbolAddress((void**)&buf1, g_buf1);

    const int Ns[3] = {256, 128, 64};
    const int Ks[3] = {512, 256, 128};

    const float* cur_in = x;
    for (int l = 0; l < 3; ++l) {
        dim3 grid(BATCH / BM, Ns[l]);
        liquid_gemm_kernel<<<grid, 256>>>(cur_in, Wi[l], bi[l], bl[l], Wo[l], bo[l],
                                          buf0, Ks[l], Ns[l]);
        lateral_kernel<<<BATCH / 16, 256>>>(buf0, Lm[l], ad[l], buf1, Ns[l]);
        cur_in = buf1;
    }
    out_kernel<<<(BATCH * OUTD + 255) / 256, 256>>>(buf1, Wout, bout, (float*)d_out);
}

// round 5
// speedup vs baseline: 2.6251x; 2.6251x over previous
#include <cuda_runtime.h>
#include <cuda_bf16.h>
#include <cstdint>

#define BATCH 4096
#define SDIM  64
#define OUTD  12
#define BM    128     // batch rows per CTA
#define BN    128     // gemm columns per CTA (= 2 neurons)
#define BKC   64      // k per chunk

// ---------------- scratch (device globals; no allocs allowed) ----------------
__device__ __align__(256) __nv_bfloat16 g_ah[BATCH * 512];   // A hi (x or h)
__device__ __align__(256) __nv_bfloat16 g_al[BATCH * 512];   // A lo
__device__ __align__(256) __nv_bfloat16 g_wth[11010048];     // W^T hi, all layers
__device__ __align__(256) __nv_bfloat16 g_wtl[11010048];     // W^T lo
__device__ __align__(256) float g_pre[BATCH * 256];
__device__ __align__(256) float g_h[BATCH * 256];

// ---------------- helpers ----------------
__device__ __forceinline__ uint32_t smem_u32(const void* p) {
    uint32_t a;
    asm("{ .reg .u64 t; cvta.to.shared.u64 t, %1; cvt.u32.u64 %0, t; }" : "=r"(a) : "l"(p));
    return a;
}
__device__ __forceinline__ void cp16(uint32_t s, const void* g) {
    asm volatile("cp.async.cg.shared.global [%0], [%1], 16;" :: "r"(s), "l"(g));
}
#define CP_COMMIT() asm volatile("cp.async.commit_group;" ::: "memory")
#define CP_WAIT(n)  asm volatile("cp.async.wait_group %0;" :: "n"(n) : "memory")

__device__ __forceinline__ void ldm_x4(uint32_t* r, uint32_t addr) {
    asm volatile("ldmatrix.sync.aligned.m8n8.x4.shared.b16 {%0,%1,%2,%3}, [%4];"
                 : "=r"(r[0]), "=r"(r[1]), "=r"(r[2]), "=r"(r[3]) : "r"(addr));
}
__device__ __forceinline__ void mma16816(float* d, const uint32_t* a, const uint32_t* b) {
    asm volatile("mma.sync.aligned.m16n8k16.row.col.f32.bf16.bf16.f32 "
                 "{%0,%1,%2,%3}, {%4,%5,%6,%7}, {%8,%9}, {%0,%1,%2,%3};"
                 : "+f"(d[0]), "+f"(d[1]), "+f"(d[2]), "+f"(d[3])
                 : "r"(a[0]), "r"(a[1]), "r"(a[2]), "r"(a[3]), "r"(b[0]), "r"(b[1]));
}
__device__ __forceinline__ uint32_t swz(uint32_t off) {   // SW128: rows of 128B
    return off ^ ((off >> 3) & 0x70);
}
// activation: tanh(v) + 0.1*sin(0.5v)*cos(0.3v); tanh via ex2+rcp (accurate)
__device__ __forceinline__ float liquid_act(float v) {
    float e, r, s, c;
    asm("ex2.approx.f32 %0, %1;" : "=f"(e) : "f"(v * 2.8853900817779268f));
    asm("rcp.approx.f32 %0, %1;" : "=f"(r) : "f"(e + 1.0f));
    float t = 1.0f - 2.0f * r;
    asm("sin.approx.f32 %0, %1;" : "=f"(s) : "f"(0.5f * v));
    asm("cos.approx.f32 %0, %1;" : "=f"(c) : "f"(0.3f * v));
    return t + 0.1f * s * c;
}

// smem layout (dynamic): A stages @0,@16384; B stages @32768,@49152;
// bias @65536 (128 f32); wo @66048 (128 f32); psum @66560 (128*4 f32)
#define SM_B_OFF   32768
#define SM_BIAS    65536
#define SM_WO      66048
#define SM_PSUM    66560
#define SM_TOTAL   68608

// GEMM (hi/lo 3-pass, HMMA) + fused activation/output-projection epilogue.
// grid: (BATCH/BM, (N*64)/BN), 256 threads (8 warps: 2 along M x 4 along ncols)
__global__ void __launch_bounds__(256)
liquid_mma_kernel(const __nv_bfloat16* __restrict__ Ah, const __nv_bfloat16* __restrict__ Al,
                  const __nv_bfloat16* __restrict__ Bth, const __nv_bfloat16* __restrict__ Btl,
                  const float* __restrict__ bi, const float* __restrict__ bl,
                  const float* __restrict__ Wo, const float* __restrict__ bo,
                  float* __restrict__ pre, int K, int Nn)
{
    extern __shared__ char smem[];
    const uint32_t sb = smem_u32(smem);
    const int tid = threadIdx.x;
    const int wid  = tid >> 5;
    const int lane = tid & 31;
    const int wm = wid >> 2;          // 0-1: m offset wm*64
    const int wn = wid & 3;           // 0-3: n offset wn*32
    const int b0    = blockIdx.x * BM;
    const int ncol0 = blockIdx.y * BN;

    // bias + wo for this CTA's 128 columns
    if (tid < 128) {
        int gc = ncol0 + tid;
        int nn = gc >> 6, s = gc & 63;
        ((float*)(smem + SM_BIAS))[tid] = bi[nn * SDIM + s] + bl[nn * SDIM + s];
        ((float*)(smem + SM_WO))[tid]   = Wo[nn * SDIM + s];
    }

    float d[4][4][4];
    #pragma unroll
    for (int mi = 0; mi < 4; ++mi)
        #pragma unroll
        for (int nj = 0; nj < 4; ++nj)
            #pragma unroll
            for (int c = 0; c < 4; ++c) d[mi][nj][c] = 0.f;

    const int chunks = K >> 6;
    const int niters = 3 * chunks;

    // per-thread load slots: 4 lines of 16B each for A and B
    const int lrow = tid >> 3;        // 0..31 (+32*i)
    const int lseg = tid & 7;

    // ldmatrix lane address components
    const int a_row = wm * 64 + (lane & 15);
    const int a_cb  = (lane >> 4) * 16;
    const int b_row = wn * 32 + (lane & 7) + ((lane >> 4) << 3);
    const int b_cb  = ((lane >> 3) & 1) * 16;

    auto issue_loads = [&](int it) {
        const int pass = it / chunks;
        const int k0   = (it - pass * chunks) << 6;
        const int sp   = it & 1;
        const __nv_bfloat16* As = (pass == 2) ? Al : Ah;
        const __nv_bfloat16* Bs = (pass == 1) ? Btl : Bth;
        uint32_t sA = sb + sp * 16384;
        uint32_t sB = sb + SM_B_OFF + sp * 16384;
        #pragma unroll
        for (int i = 0; i < 4; ++i) {
            int row = lrow + i * 32;
            uint32_t so = swz(row * 128 + lseg * 16);
            cp16(sA + so, As + (size_t)(b0 + row) * K + k0 + lseg * 8);
            cp16(sB + so, Bs + (size_t)(ncol0 + row) * K + k0 + lseg * 8);
        }
        CP_COMMIT();
    };

    issue_loads(0);

    for (int it = 0; it < niters; ++it) {
        const int sp = it & 1;
        if (it + 1 < niters) { issue_loads(it + 1); CP_WAIT(1); }
        else                 { CP_WAIT(0); }
        __syncthreads();

        uint32_t sA = sb + sp * 16384;
        uint32_t sB = sb + SM_B_OFF + sp * 16384;
        #pragma unroll
        for (int ks = 0; ks < 4; ++ks) {
            uint32_t afr[4][4], bfr[2][4];
            #pragma unroll
            for (int mi = 0; mi < 4; ++mi)
                ldm_x4(afr[mi], sA + swz((a_row + mi * 16) * 128 + ks * 32 + a_cb));
            #pragma unroll
            for (int nj2 = 0; nj2 < 2; ++nj2)
                ldm_x4(bfr[nj2], sB + swz((b_row + nj2 * 16) * 128 + ks * 32 + b_cb));
            #pragma unroll
            for (int mi = 0; mi < 4; ++mi)
                #pragma unroll
                for (int nj = 0; nj < 4; ++nj)
                    mma16816(d[mi][nj], afr[mi], &bfr[nj >> 1][(nj & 1) * 2]);
        }
        __syncthreads();
    }

    // ---- epilogue: act + Wo dot, reduce over this CTA's 128 columns ----
    {
        const int g = lane >> 2, i = lane & 3;
        const float* bs = (const float*)(smem + SM_BIAS);
        const float* ws = (const float*)(smem + SM_WO);
        float* psum = (float*)(smem + SM_PSUM);   // [128][4]

        #pragma unroll
        for (int mi = 0; mi < 4; ++mi) {
            float p0 = 0.f, p1 = 0.f;
            #pragma unroll
            for (int nj = 0; nj < 4; ++nj) {
                int c = wn * 32 + nj * 8 + 2 * i;
                float w0 = ws[c], w1 = ws[c + 1];
                float bb0 = bs[c], bb1 = bs[c + 1];
                p0 += liquid_act(d[mi][nj][0] + bb0) * w0 + liquid_act(d[mi][nj][1] + bb1) * w1;
                p1 += liquid_act(d[mi][nj][2] + bb0) * w0 + liquid_act(d[mi][nj][3] + bb1) * w1;
            }
            p0 += __shfl_xor_sync(0xffffffffu, p0, 1);
            p0 += __shfl_xor_sync(0xffffffffu, p0, 2);
            p1 += __shfl_xor_sync(0xffffffffu, p1, 1);
            p1 += __shfl_xor_sync(0xffffffffu, p1, 2);
            if (i == 0) {
                int r = wm * 64 + mi * 16 + g;
                psum[r * 4 + wn]       = p0;
                psum[(r + 8) * 4 + wn] = p1;
            }
        }
        __syncthreads();

        int row  = tid >> 1;
        int half = tid & 1;
        int neuron = blockIdx.y * 2 + half;
        float val = psum[row * 4 + half * 2] + psum[row * 4 + half * 2 + 1] + bo[neuron];
        pre[(size_t)(b0 + row) * Nn + neuron] = val;
    }
}

// ---------------- weight transpose + hi/lo split: Wi[n][k][s] -> Wt[n*64+s][k] ----------------
__global__ __launch_bounds__(256)
void wsplit_kernel(const float* __restrict__ Wi, __nv_bfloat16* __restrict__ Wth,
                   __nv_bfloat16* __restrict__ Wtl, int K)
{
    const int n  = blockIdx.y;
    const int k0 = blockIdx.x * 64;
    __shared__ float tile[64][65];
    const float* src = Wi + ((size_t)n * K + k0) * SDIM;
    for (int i = threadIdx.x; i < 4096; i += 256) {
        int kk = i >> 6, s = i & 63;
        tile[kk][s] = src[kk * SDIM + s];
    }
    __syncthreads();
    for (int i = threadIdx.x; i < 4096; i += 256) {
        int s = i >> 6, kk = i & 63;
        float v = tile[kk][s];
        __nv_bfloat16 h = __float2bfloat16(v);
        size_t o = (size_t)n * SDIM * K + (size_t)s * K + k0 + kk;
        Wth[o] = h;
        Wtl[o] = __float2bfloat16(v - __bfloat162float(h));
    }
}

// ---------------- x hi/lo split ----------------
__global__ __launch_bounds__(256)
void xsplit_kernel(const float* __restrict__ x, __nv_bfloat16* __restrict__ xh,
                   __nv_bfloat16* __restrict__ xl, int n)
{
    int i = blockIdx.x * 256 + threadIdx.x;
    if (i >= n) return;
    float v = x[i];
    __nv_bfloat16 h = __float2bfloat16(v);
    xh[i] = h;
    xl[i] = __float2bfloat16(v - __bfloat162float(h));
}

// ---------------- lateral mixing (f32x2 pairs); also emits bf16 hi/lo ----------------
__global__ __launch_bounds__(256)
void lateral_kernel(const float* __restrict__ pre, const float* __restrict__ L,
                    const float* __restrict__ a, float* __restrict__ h,
                    __nv_bfloat16* __restrict__ hh, __nv_bfloat16* __restrict__ hl, int N)
{
    const int b0  = blockIdx.x * 32;
    const int tid = threadIdx.x;
    __shared__ float ps[32 * 256];

    for (int idx = tid; idx < 32 * N; idx += 256)
        ps[idx] = pre[(size_t)(b0 + idx / N) * N + (idx % N)];
    __syncthreads();

    const int half = N >> 1;
    for (int it = tid; it < 32 * half; it += 256) {
        int r  = it / half;
        int np = it - r * half;
        int n  = np * 2;
        const float* pr = ps + r * N;
        unsigned long long acc = 0ull;
        #pragma unroll 4
        for (int m = 0; m < N; ++m) {
            unsigned long long lp = *(const unsigned long long*)(L + (size_t)m * N + n);
            unsigned long long ap;
            asm("mov.b64 %0, {%1, %1};" : "=l"(ap) : "r"(__float_as_uint(pr[m])));
            asm("fma.rn.f32x2 %0, %1, %2, %0;" : "+l"(acc) : "l"(ap), "l"(lp));
        }
        float s0 = __uint_as_float((unsigned)(acc & 0xffffffffull));
        float s1 = __uint_as_float((unsigned)(acc >> 32));
        float v0 = (pr[n]     + 0.1f * s0) * a[n];
        float v1 = (pr[n + 1] + 0.1f * s1) * a[n + 1];
        size_t o = (size_t)(b0 + r) * N + n;
        h[o] = v0; h[o + 1] = v1;
        __nv_bfloat16 h0 = __float2bfloat16(v0);
        __nv_bfloat16 h1 = __float2bfloat16(v1);
        hh[o] = h0; hh[o + 1] = h1;
        hl[o]     = __float2bfloat16(v0 - __bfloat162float(h0));
        hl[o + 1] = __float2bfloat16(v1 - __bfloat162float(h1));
    }
}

// ---------------- final projection ----------------
__global__ __launch_bounds__(256)
void out_kernel(const float* __restrict__ h, const float* __restrict__ Wout,
                const float* __restrict__ bout, float* __restrict__ y)
{
    int idx = blockIdx.x * blockDim.x + threadIdx.x;
    if (idx >= BATCH * OUTD) return;
    int b = idx / OUTD;
    int o = idx - b * OUTD;
    const float* hb = h + (size_t)b * 64;
    float s = bout[o];
    #pragma unroll
    for (int m = 0; m < 64; ++m)
        s += hb[m] * Wout[m * OUTD + o];
    y[idx] = s;
}

extern "C" void kernel_launch(void* const* d_in, const int* in_sizes, int n_in,
                              void* d_out, int out_size)
{
    (void)in_sizes; (void)n_in; (void)out_size;
    const float* x = (const float*)d_in[0];
    const float *Wi[3], *bi[3], *bl[3], *Wo[3], *bo[3], *Lm[3], *ad[3];
    for (int l = 0; l < 3; ++l) {
        int base = 1 + 7 * l;
        Wi[l] = (const float*)d_in[base + 0];
        bi[l] = (const float*)d_in[base + 1];
        bl[l] = (const float*)d_in[base + 2];
        Wo[l] = (const float*)d_in[base + 3];
        bo[l] = (const float*)d_in[base + 4];
        Lm[l] = (const float*)d_in[base + 5];
        ad[l] = (const float*)d_in[base + 6];
    }
    const float* Wout = (const float*)d_in[22];
    const float* bout = (const float*)d_in[23];

    __nv_bfloat16 *ah, *al, *wth, *wtl;
    float *pre, *h;
    cudaGetSymbolAddress((void**)&ah,  g_ah);
    cudaGetSymbolAddress((void**)&al,  g_al);
    cudaGetSymbolAddress((void**)&wth, g_wth);
    cudaGetSymbolAddress((void**)&wtl, g_wtl);
    cudaGetSymbolAddress((void**)&pre, g_pre);
    cudaGetSymbolAddress((void**)&h,   g_h);

    cudaFuncSetAttribute(liquid_mma_kernel, cudaFuncAttributeMaxDynamicSharedMemorySize, SM_TOTAL);

    const int Ns[3] = {256, 128, 64};
    const int Ks[3] = {512, 256, 128};
    const size_t woff[3] = {0, 8388608, 10485760};

    for (int l = 0; l < 3; ++l) {
        dim3 g(Ks[l] / 64, Ns[l]);
        wsplit_kernel<<<g, 256>>>(Wi[l], wth + woff[l], wtl + woff[l], Ks[l]);
    }
    xsplit_kernel<<<(BATCH * 512) / 256, 256>>>(x, ah, al, BATCH * 512);

    for (int l = 0; l < 3; ++l) {
        dim3 grid(BATCH / BM, (Ns[l] * SDIM) / BN);   // = Ns[l]/2
        liquid_mma_kernel<<<grid, 256, SM_TOTAL>>>(ah, al, wth + woff[l], wtl + woff[l],
                                                   bi[l], bl[l], Wo[l], bo[l], pre,
                                                   Ks[l], Ns[l]);
        lateral_kernel<<<BATCH / 32, 256>>>(pre, Lm[l], ad[l], h, ah, al, Ns[l]);
    }
    out_kernel<<<(BATCH * OUTD + 255) / 256, 256>>>(h, Wout, bout, (float*)d_out);
}

// round 6
// speedup vs baseline: 5.3557x; 2.0402x over previous
#include <cuda_runtime.h>
#include <cuda_fp16.h>
#include <cstdint>

#define BATCH 4096
#define SDIM  64
#define OUTD  12
#define BM    128     // batch rows per CTA
#define BN    128     // gemm columns per CTA (= 2 neurons)

// ---------------- scratch (device globals; no allocs allowed) ----------------
__device__ __align__(256) __half g_ah[BATCH * 512];    // A fp16 (x or h)
__device__ __align__(256) __half g_wth[11010048];      // W^T fp16, all layers
__device__ __align__(256) float  g_pre[BATCH * 256];
__device__ __align__(256) float  g_h[BATCH * 256];

// ---------------- helpers ----------------
__device__ __forceinline__ uint32_t smem_u32(const void* p) {
    uint32_t a;
    asm("{ .reg .u64 t; cvta.to.shared.u64 t, %1; cvt.u32.u64 %0, t; }" : "=r"(a) : "l"(p));
    return a;
}
__device__ __forceinline__ void cp16(uint32_t s, const void* g) {
    asm volatile("cp.async.cg.shared.global [%0], [%1], 16;" :: "r"(s), "l"(g));
}
#define CP_COMMIT() asm volatile("cp.async.commit_group;" ::: "memory")
#define CP_WAIT(n)  asm volatile("cp.async.wait_group %0;" :: "n"(n) : "memory")

__device__ __forceinline__ void ldm_x4(uint32_t* r, uint32_t addr) {
    asm volatile("ldmatrix.sync.aligned.m8n8.x4.shared.b16 {%0,%1,%2,%3}, [%4];"
                 : "=r"(r[0]), "=r"(r[1]), "=r"(r[2]), "=r"(r[3]) : "r"(addr));
}
__device__ __forceinline__ void mma16816(float* d, const uint32_t* a, const uint32_t* b) {
    asm volatile("mma.sync.aligned.m16n8k16.row.col.f32.f16.f16.f32 "
                 "{%0,%1,%2,%3}, {%4,%5,%6,%7}, {%8,%9}, {%0,%1,%2,%3};"
                 : "+f"(d[0]), "+f"(d[1]), "+f"(d[2]), "+f"(d[3])
                 : "r"(a[0]), "r"(a[1]), "r"(a[2]), "r"(a[3]), "r"(b[0]), "r"(b[1]));
}
__device__ __forceinline__ uint32_t swz(uint32_t off) {   // SW128: rows of 128B
    return off ^ ((off >> 3) & 0x70);
}
// activation: tanh(v) + 0.1*sin(0.5v)*cos(0.3v); tanh via ex2+rcp (accurate)
__device__ __forceinline__ float liquid_act(float v) {
    float e, r, s, c;
    asm("ex2.approx.f32 %0, %1;" : "=f"(e) : "f"(v * 2.8853900817779268f));
    asm("rcp.approx.f32 %0, %1;" : "=f"(r) : "f"(e + 1.0f));
    float t = 1.0f - 2.0f * r;
    asm("sin.approx.f32 %0, %1;" : "=f"(s) : "f"(0.5f * v));
    asm("cos.approx.f32 %0, %1;" : "=f"(c) : "f"(0.3f * v));
    return t + 0.1f * s * c;
}

// smem layout (dynamic): A stages @0,@16384; B stages @32768,@49152;
// bias @65536 (128 f32); wo @66048 (128 f32); psum @66560 (128*4 f32)
#define SM_B_OFF   32768
#define SM_BIAS    65536
#define SM_WO      66048
#define SM_PSUM    66560
#define SM_TOTAL   68608

// Single-pass fp16 HMMA GEMM + fused activation/output-projection epilogue.
// grid: (BATCH/BM, (N*64)/BN), 256 threads (8 warps: 2 along M x 4 along ncols)
__global__ void __launch_bounds__(256, 2)
liquid_mma_kernel(const __half* __restrict__ Ah, const __half* __restrict__ Bth,
                  const float* __restrict__ bi, const float* __restrict__ bl,
                  const float* __restrict__ Wo, const float* __restrict__ bo,
                  float* __restrict__ pre, int K, int Nn)
{
    extern __shared__ char smem[];
    const uint32_t sb = smem_u32(smem);
    const int tid = threadIdx.x;
    const int wid  = tid >> 5;
    const int lane = tid & 31;
    const int wm = wid >> 2;          // 0-1: m offset wm*64
    const int wn = wid & 3;           // 0-3: n offset wn*32
    const int b0    = blockIdx.x * BM;
    const int ncol0 = blockIdx.y * BN;

    // bias + wo for this CTA's 128 columns
    if (tid < 128) {
        int gc = ncol0 + tid;
        int nn = gc >> 6, s = gc & 63;
        ((float*)(smem + SM_BIAS))[tid] = bi[nn * SDIM + s] + bl[nn * SDIM + s];
        ((float*)(smem + SM_WO))[tid]   = Wo[nn * SDIM + s];
    }

    float d[4][4][4];
    #pragma unroll
    for (int mi = 0; mi < 4; ++mi)
        #pragma unroll
        for (int nj = 0; nj < 4; ++nj)
            #pragma unroll
            for (int c = 0; c < 4; ++c) d[mi][nj][c] = 0.f;

    const int niters = K >> 6;

    // per-thread load slots: 4 lines of 16B each for A and B
    const int lrow = tid >> 3;        // 0..31 (+32*i)
    const int lseg = tid & 7;

    // ldmatrix lane address components
    const int a_row = wm * 64 + (lane & 15);
    const int a_cb  = (lane >> 4) * 16;
    const int b_row = wn * 32 + (lane & 7) + ((lane >> 4) << 3);
    const int b_cb  = ((lane >> 3) & 1) * 16;

    auto issue_loads = [&](int it) {
        const int k0 = it << 6;
        const int sp = it & 1;
        uint32_t sA = sb + sp * 16384;
        uint32_t sB = sb + SM_B_OFF + sp * 16384;
        #pragma unroll
        for (int i = 0; i < 4; ++i) {
            int row = lrow + i * 32;
            uint32_t so = swz(row * 128 + lseg * 16);
            cp16(sA + so, Ah  + (size_t)(b0 + row) * K + k0 + lseg * 8);
            cp16(sB + so, Bth + (size_t)(ncol0 + row) * K + k0 + lseg * 8);
        }
        CP_COMMIT();
    };

    issue_loads(0);

    for (int it = 0; it < niters; ++it) {
        const int sp = it & 1;
        if (it + 1 < niters) { issue_loads(it + 1); CP_WAIT(1); }
        else                 { CP_WAIT(0); }
        __syncthreads();

        uint32_t sA = sb + sp * 16384;
        uint32_t sB = sb + SM_B_OFF + sp * 16384;
        #pragma unroll
        for (int ks = 0; ks < 4; ++ks) {
            uint32_t afr[4][4], bfr[2][4];
            #pragma unroll
            for (int mi = 0; mi < 4; ++mi)
                ldm_x4(afr[mi], sA + swz((a_row + mi * 16) * 128 + ks * 32 + a_cb));
            #pragma unroll
            for (int nj2 = 0; nj2 < 2; ++nj2)
                ldm_x4(bfr[nj2], sB + swz((b_row + nj2 * 16) * 128 + ks * 32 + b_cb));
            #pragma unroll
            for (int mi = 0; mi < 4; ++mi)
                #pragma unroll
                for (int nj = 0; nj < 4; ++nj)
                    mma16816(d[mi][nj], afr[mi], &bfr[nj >> 1][(nj & 1) * 2]);
        }
        __syncthreads();
    }

    // ---- epilogue: act + Wo dot, reduce over this CTA's 128 columns ----
    {
        const int g = lane >> 2, i = lane & 3;
        const float* bs = (const float*)(smem + SM_BIAS);
        const float* ws = (const float*)(smem + SM_WO);
        float* psum = (float*)(smem + SM_PSUM);   // [128][4]

        #pragma unroll
        for (int mi = 0; mi < 4; ++mi) {
            float p0 = 0.f, p1 = 0.f;
            #pragma unroll
            for (int nj = 0; nj < 4; ++nj) {
                int c = wn * 32 + nj * 8 + 2 * i;
                float w0 = ws[c], w1 = ws[c + 1];
                float bb0 = bs[c], bb1 = bs[c + 1];
                p0 += liquid_act(d[mi][nj][0] + bb0) * w0 + liquid_act(d[mi][nj][1] + bb1) * w1;
                p1 += liquid_act(d[mi][nj][2] + bb0) * w0 + liquid_act(d[mi][nj][3] + bb1) * w1;
            }
            p0 += __shfl_xor_sync(0xffffffffu, p0, 1);
            p0 += __shfl_xor_sync(0xffffffffu, p0, 2);
            p1 += __shfl_xor_sync(0xffffffffu, p1, 1);
            p1 += __shfl_xor_sync(0xffffffffu, p1, 2);
            if (i == 0) {
                int r = wm * 64 + mi * 16 + g;
                psum[r * 4 + wn]       = p0;
                psum[(r + 8) * 4 + wn] = p1;
            }
        }
        __syncthreads();

        int row  = tid >> 1;
        int half = tid & 1;
        int neuron = blockIdx.y * 2 + half;
        float val = psum[row * 4 + half * 2] + psum[row * 4 + half * 2 + 1] + bo[neuron];
        pre[(size_t)(b0 + row) * Nn + neuron] = val;
    }
}

// ---------------- weight transpose to fp16: Wi[n][k][s] -> Wt[n*64+s][k] ----------------
__global__ __launch_bounds__(256)
void wsplit_kernel(const float* __restrict__ Wi, __half* __restrict__ Wth, int K)
{
    const int n  = blockIdx.y;
    const int k0 = blockIdx.x * 64;
    __shared__ float tile[64][65];
    const float* src = Wi + ((size_t)n * K + k0) * SDIM;
    for (int i = threadIdx.x; i < 4096; i += 256) {
        int kk = i >> 6, s = i & 63;
        tile[kk][s] = src[kk * SDIM + s];
    }
    __syncthreads();
    for (int i = threadIdx.x; i < 4096; i += 256) {
        int s = i >> 6, kk = i & 63;
        Wth[(size_t)n * SDIM * K + (size_t)s * K + k0 + kk] = __float2half(tile[kk][s]);
    }
}

// ---------------- x -> fp16 ----------------
__global__ __launch_bounds__(256)
void xsplit_kernel(const float* __restrict__ x, __half* __restrict__ xh, int n)
{
    int i = blockIdx.x * 256 + threadIdx.x;
    if (i < n) xh[i] = __float2half(x[i]);
}

// ---------------- lateral mixing (f32x2 pairs); also emits fp16 for next layer ----------------
__global__ __launch_bounds__(256)
void lateral_kernel(const float* __restrict__ pre, const float* __restrict__ L,
                    const float* __restrict__ a, float* __restrict__ h,
                    __half* __restrict__ hh, int N)
{
    const int b0  = blockIdx.x * 32;
    const int tid = threadIdx.x;
    __shared__ float ps[32 * 256];

    for (int idx = tid; idx < 32 * N; idx += 256)
        ps[idx] = pre[(size_t)(b0 + idx / N) * N + (idx % N)];
    __syncthreads();

    const int half = N >> 1;
    for (int it = tid; it < 32 * half; it += 256) {
        int r  = it / half;
        int np = it - r * half;
        int n  = np * 2;
        const float* pr = ps + r * N;
        unsigned long long acc = 0ull;
        #pragma unroll 4
        for (int m = 0; m < N; ++m) {
            unsigned long long lp = *(const unsigned long long*)(L + (size_t)m * N + n);
            unsigned long long ap;
            asm("mov.b64 %0, {%1, %1};" : "=l"(ap) : "r"(__float_as_uint(pr[m])));
            asm("fma.rn.f32x2 %0, %1, %2, %0;" : "+l"(acc) : "l"(ap), "l"(lp));
        }
        float s0 = __uint_as_float((unsigned)(acc & 0xffffffffull));
        float s1 = __uint_as_float((unsigned)(acc >> 32));
        float v0 = (pr[n]     + 0.1f * s0) * a[n];
        float v1 = (pr[n + 1] + 0.1f * s1) * a[n + 1];
        size_t o = (size_t)(b0 + r) * N + n;
        h[o] = v0; h[o + 1] = v1;
        hh[o] = __float2half(v0); hh[o + 1] = __float2half(v1);
    }
}

// ---------------- final projection ----------------
__global__ __launch_bounds__(256)
void out_kernel(const float* __restrict__ h, const float* __restrict__ Wout,
                const float* __restrict__ bout, float* __restrict__ y)
{
    int idx = blockIdx.x * blockDim.x + threadIdx.x;
    if (idx >= BATCH * OUTD) return;
    int b = idx / OUTD;
    int o = idx - b * OUTD;
    const float* hb = h + (size_t)b * 64;
    float s = bout[o];
    #pragma unroll
    for (int m = 0; m < 64; ++m)
        s += hb[m] * Wout[m * OUTD + o];
    y[idx] = s;
}

extern "C" void kernel_launch(void* const* d_in, const int* in_sizes, int n_in,
                              void* d_out, int out_size)
{
    (void)in_sizes; (void)n_in; (void)out_size;
    const float* x = (const float*)d_in[0];
    const float *Wi[3], *bi[3], *bl[3], *Wo[3], *bo[3], *Lm[3], *ad[3];
    for (int l = 0; l < 3; ++l) {
        int base = 1 + 7 * l;
        Wi[l] = (const float*)d_in[base + 0];
        bi[l] = (const float*)d_in[base + 1];
        bl[l] = (const float*)d_in[base + 2];
        Wo[l] = (const float*)d_in[base + 3];
        bo[l] = (const float*)d_in[base + 4];
        Lm[l] = (const float*)d_in[base + 5];
        ad[l] = (const float*)d_in[base + 6];
    }
    const float* Wout = (const float*)d_in[22];
    const float* bout = (const float*)d_in[23];

    __half *ah, *wth;
    float *pre, *h;
    cudaGetSymbolAddress((void**)&ah,  g_ah);
    cudaGetSymbolAddress((void**)&wth, g_wth);
    cudaGetSymbolAddress((void**)&pre, g_pre);
    cudaGetSymbolAddress((void**)&h,   g_h);

    cudaFuncSetAttribute(liquid_mma_kernel, cudaFuncAttributeMaxDynamicSharedMemorySize, SM_TOTAL);

    const int Ns[3] = {256, 128, 64};
    const int Ks[3] = {512, 256, 128};
    const size_t woff[3] = {0, 8388608, 10485760};

    for (int l = 0; l < 3; ++l) {
        dim3 g(Ks[l] / 64, Ns[l]);
        wsplit_kernel<<<g, 256>>>(Wi[l], wth + woff[l], Ks[l]);
    }
    xsplit_kernel<<<(BATCH * 512) / 256, 256>>>(x, ah, BATCH * 512);

    for (int l = 0; l < 3; ++l) {
        dim3 grid(BATCH / BM, (Ns[l] * SDIM) / BN);   // = Ns[l]/2
        liquid_mma_kernel<<<grid, 256, SM_TOTAL>>>(ah, wth + woff[l],
                                                   bi[l], bl[l], Wo[l], bo[l], pre,
                                                   Ks[l], Ns[l]);
        lateral_kernel<<<BATCH / 32, 256>>>(pre, Lm[l], ad[l], h, ah, Ns[l]);
    }
    out_kernel<<<(BATCH * OUTD + 255) / 256, 256>>>(h, Wout, bout, (float*)d_out);
}

// round 7
// speedup vs baseline: 5.5007x; 1.0271x over previous
#include <cuda_runtime.h>
#include <cuda_fp16.h>
#include <cstdint>

#define BATCH 4096
#define SDIM  64
#define OUTD  12
#define BM    128     // batch rows per CTA
#define BN    128     // gemm columns per CTA (= 2 neurons)

// ---------------- scratch (device globals; no allocs allowed) ----------------
__device__ __align__(256) __half g_ah[BATCH * 512];    // A fp16 (x or h)
__device__ __align__(256) __half g_wth[11010048];      // W^T fp16, all layers
__device__ __align__(256) float  g_pre[BATCH * 256];
__device__ __align__(256) float  g_h[BATCH * 256];

// ---------------- helpers ----------------
__device__ __forceinline__ uint32_t smem_u32(const void* p) {
    uint32_t a;
    asm("{ .reg .u64 t; cvta.to.shared.u64 t, %1; cvt.u32.u64 %0, t; }" : "=r"(a) : "l"(p));
    return a;
}
__device__ __forceinline__ void cp16(uint32_t s, const void* g) {
    asm volatile("cp.async.cg.shared.global [%0], [%1], 16;" :: "r"(s), "l"(g));
}
#define CP_COMMIT() asm volatile("cp.async.commit_group;" ::: "memory")
#define CP_WAIT(n)  asm volatile("cp.async.wait_group %0;" :: "n"(n) : "memory")

__device__ __forceinline__ void ldm_x4(uint32_t* r, uint32_t addr) {
    asm volatile("ldmatrix.sync.aligned.m8n8.x4.shared.b16 {%0,%1,%2,%3}, [%4];"
                 : "=r"(r[0]), "=r"(r[1]), "=r"(r[2]), "=r"(r[3]) : "r"(addr));
}
__device__ __forceinline__ void mma16816(float* d, const uint32_t* a, const uint32_t* b) {
    asm volatile("mma.sync.aligned.m16n8k16.row.col.f32.f16.f16.f32 "
                 "{%0,%1,%2,%3}, {%4,%5,%6,%7}, {%8,%9}, {%0,%1,%2,%3};"
                 : "+f"(d[0]), "+f"(d[1]), "+f"(d[2]), "+f"(d[3])
                 : "r"(a[0]), "r"(a[1]), "r"(a[2]), "r"(a[3]), "r"(b[0]), "r"(b[1]));
}
__device__ __forceinline__ uint32_t swz(uint32_t off) {   // SW128: rows of 128B
    return off ^ ((off >> 3) & 0x70);
}
// activation: tanh(v) + 0.1*sin(0.5v)*cos(0.3v); tanh.approx MUFU
__device__ __forceinline__ float liquid_act(float v) {
    float t, s, c;
    asm("tanh.approx.f32 %0, %1;" : "=f"(t) : "f"(v));
    asm("sin.approx.f32 %0, %1;" : "=f"(s) : "f"(0.5f * v));
    asm("cos.approx.f32 %0, %1;" : "=f"(c) : "f"(0.3f * v));
    return t + 0.1f * s * c;
}

// smem layout (dynamic): A stages @0/16384/32768 (16KB each);
// B stages @49152/65536/81920; bias @98304 (128 f32); wo @98816; psum @99328 (2KB)
#define SM_B_OFF   49152
#define SM_BIAS    98304
#define SM_WO      98816
#define SM_PSUM    99328
#define SM_TOTAL   101376

// Single-pass fp16 HMMA GEMM + fused activation/output-projection epilogue.
// grid: (BATCH/BM, (N*64)/BN), 256 threads (8 warps: 2 along M x 4 along ncols)
__global__ void __launch_bounds__(256, 2)
liquid_mma_kernel(const __half* __restrict__ Ah, const __half* __restrict__ Bth,
                  const float* __restrict__ bi, const float* __restrict__ bl,
                  const float* __restrict__ Wo, const float* __restrict__ bo,
                  float* __restrict__ pre, int K, int Nn)
{
    extern __shared__ char smem[];
    const uint32_t sb = smem_u32(smem);
    const int tid = threadIdx.x;
    const int wid  = tid >> 5;
    const int lane = tid & 31;
    const int wm = wid >> 2;          // 0-1: m offset wm*64
    const int wn = wid & 3;           // 0-3: n offset wn*32
    const int b0    = blockIdx.x * BM;
    const int ncol0 = blockIdx.y * BN;

    // bias + wo for this CTA's 128 columns
    if (tid < 128) {
        int gc = ncol0 + tid;
        int nn = gc >> 6, s = gc & 63;
        ((float*)(smem + SM_BIAS))[tid] = bi[nn * SDIM + s] + bl[nn * SDIM + s];
        ((float*)(smem + SM_WO))[tid]   = Wo[nn * SDIM + s];
    }

    float d[4][4][4];
    #pragma unroll
    for (int mi = 0; mi < 4; ++mi)
        #pragma unroll
        for (int nj = 0; nj < 4; ++nj)
            #pragma unroll
            for (int c = 0; c < 4; ++c) d[mi][nj][c] = 0.f;

    const int niters = K >> 6;

    // per-thread load slots: 4 lines of 16B each for A and B
    const int lrow = tid >> 3;        // 0..31 (+32*i)
    const int lseg = tid & 7;

    // ldmatrix lane address components
    const int a_row = wm * 64 + (lane & 15);
    const int a_cb  = (lane >> 4) * 16;
    const int b_row = wn * 32 + (lane & 7) + ((lane >> 4) << 3);
    const int b_cb  = ((lane >> 3) & 1) * 16;

    auto issue_loads = [&](int it, int st) {
        const int k0 = it << 6;
        uint32_t sA = sb + st * 16384;
        uint32_t sB = sb + SM_B_OFF + st * 16384;
        #pragma unroll
        for (int i = 0; i < 4; ++i) {
            int row = lrow + i * 32;
            uint32_t so = swz(row * 128 + lseg * 16);
            cp16(sA + so, Ah  + (size_t)(b0 + row) * K + k0 + lseg * 8);
            cp16(sB + so, Bth + (size_t)(ncol0 + row) * K + k0 + lseg * 8);
        }
        CP_COMMIT();
    };

    issue_loads(0, 0);
    if (niters > 1) issue_loads(1, 1);

    int cur = 0;
    for (int it = 0; it < niters; ++it) {
        if (it == niters - 1) { CP_WAIT(0); } else { CP_WAIT(1); }
        __syncthreads();
        if (it + 2 < niters) {
            int nx = cur + 2; if (nx >= 3) nx -= 3;
            issue_loads(it + 2, nx);
        }

        uint32_t sA = sb + cur * 16384;
        uint32_t sB = sb + SM_B_OFF + cur * 16384;
        #pragma unroll
        for (int ks = 0; ks < 4; ++ks) {
            uint32_t afr[4][4], bfr[2][4];
            #pragma unroll
            for (int mi = 0; mi < 4; ++mi)
                ldm_x4(afr[mi], sA + swz((a_row + mi * 16) * 128 + ks * 32 + a_cb));
            #pragma unroll
            for (int nj2 = 0; nj2 < 2; ++nj2)
                ldm_x4(bfr[nj2], sB + swz((b_row + nj2 * 16) * 128 + ks * 32 + b_cb));
            #pragma unroll
            for (int mi = 0; mi < 4; ++mi)
                #pragma unroll
                for (int nj = 0; nj < 4; ++nj)
                    mma16816(d[mi][nj], afr[mi], &bfr[nj >> 1][(nj & 1) * 2]);
        }
        cur = (cur == 2) ? 0 : cur + 1;
    }
    __syncthreads();

    // ---- epilogue: act + Wo dot, reduce over this CTA's 128 columns ----
    {
        const int g = lane >> 2, i = lane & 3;
        const float* bs = (const float*)(smem + SM_BIAS);
        const float* ws = (const float*)(smem + SM_WO);
        float* psum = (float*)(smem + SM_PSUM);   // [128][4]

        #pragma unroll
        for (int mi = 0; mi < 4; ++mi) {
            float p0 = 0.f, p1 = 0.f;
            #pragma unroll
            for (int nj = 0; nj < 4; ++nj) {
                int c = wn * 32 + nj * 8 + 2 * i;
                float w0 = ws[c], w1 = ws[c + 1];
                float bb0 = bs[c], bb1 = bs[c + 1];
                p0 += liquid_act(d[mi][nj][0] + bb0) * w0 + liquid_act(d[mi][nj][1] + bb1) * w1;
                p1 += liquid_act(d[mi][nj][2] + bb0) * w0 + liquid_act(d[mi][nj][3] + bb1) * w1;
            }
            p0 += __shfl_xor_sync(0xffffffffu, p0, 1);
            p0 += __shfl_xor_sync(0xffffffffu, p0, 2);
            p1 += __shfl_xor_sync(0xffffffffu, p1, 1);
            p1 += __shfl_xor_sync(0xffffffffu, p1, 2);
            if (i == 0) {
                int r = wm * 64 + mi * 16 + g;
                psum[r * 4 + wn]       = p0;
                psum[(r + 8) * 4 + wn] = p1;
            }
        }
        __syncthreads();

        int row  = tid >> 1;
        int half = tid & 1;
        int neuron = blockIdx.y * 2 + half;
        float val = psum[row * 4 + half * 2] + psum[row * 4 + half * 2 + 1] + bo[neuron];
        pre[(size_t)(b0 + row) * Nn + neuron] = val;
    }
}

// ---------------- weight transpose to fp16: Wi[n][k][s] -> Wt[n*64+s][k] ----------------
__global__ __launch_bounds__(256)
void wsplit_kernel(const float* __restrict__ Wi, __half* __restrict__ Wth, int K)
{
    const int n  = blockIdx.y;
    const int k0 = blockIdx.x * 64;
    __shared__ float tile[64][65];
    const float* src = Wi + ((size_t)n * K + k0) * SDIM;
    for (int i = threadIdx.x; i < 4096; i += 256) {
        int kk = i >> 6, s = i & 63;
        tile[kk][s] = src[kk * SDIM + s];
    }
    __syncthreads();
    for (int i = threadIdx.x; i < 4096; i += 256) {
        int s = i >> 6, kk = i & 63;
        Wth[(size_t)n * SDIM * K + (size_t)s * K + k0 + kk] = __float2half(tile[kk][s]);
    }
}

// ---------------- x -> fp16 (vectorized, 4 elems/thread) ----------------
__global__ __launch_bounds__(256)
void xsplit_kernel(const float* __restrict__ x, __half* __restrict__ xh, int n4)
{
    int i = blockIdx.x * 256 + threadIdx.x;
    if (i >= n4) return;
    float4 v = ((const float4*)x)[i];
    __half2 lo = __floats2half2_rn(v.x, v.y);
    __half2 hi = __floats2half2_rn(v.z, v.w);
    ((__half2*)xh)[2 * i]     = lo;
    ((__half2*)xh)[2 * i + 1] = hi;
}

// ---------------- lateral mixing (f32x2 pairs); also emits fp16 for next layer ----------------
__global__ __launch_bounds__(256)
void lateral_kernel(const float* __restrict__ pre, const float* __restrict__ L,
                    const float* __restrict__ a, float* __restrict__ h,
                    __half* __restrict__ hh, int N)
{
    const int b0  = blockIdx.x * 32;
    const int tid = threadIdx.x;
    __shared__ float ps[32 * 256];

    for (int idx = tid; idx < 32 * N; idx += 256)
        ps[idx] = pre[(size_t)(b0 + idx / N) * N + (idx % N)];
    __syncthreads();

    const int half = N >> 1;
    for (int it = tid; it < 32 * half; it += 256) {
        int r  = it / half;
        int np = it - r * half;
        int n  = np * 2;
        const float* pr = ps + r * N;
        unsigned long long acc = 0ull;
        #pragma unroll 4
        for (int m = 0; m < N; ++m) {
            unsigned long long lp = *(const unsigned long long*)(L + (size_t)m * N + n);
            unsigned long long ap;
            asm("mov.b64 %0, {%1, %1};" : "=l"(ap) : "r"(__float_as_uint(pr[m])));
            asm("fma.rn.f32x2 %0, %1, %2, %0;" : "+l"(acc) : "l"(ap), "l"(lp));
        }
        float s0 = __uint_as_float((unsigned)(acc & 0xffffffffull));
        float s1 = __uint_as_float((unsigned)(acc >> 32));
        float v0 = (pr[n]     + 0.1f * s0) * a[n];
        float v1 = (pr[n + 1] + 0.1f * s1) * a[n + 1];
        size_t o = (size_t)(b0 + r) * N + n;
        h[o] = v0; h[o + 1] = v1;
        hh[o] = __float2half(v0); hh[o + 1] = __float2half(v1);
    }
}

// ---------------- final projection ----------------
__global__ __launch_bounds__(256)
void out_kernel(const float* __restrict__ h, const float* __restrict__ Wout,
                const float* __restrict__ bout, float* __restrict__ y)
{
    int idx = blockIdx.x * blockDim.x + threadIdx.x;
    if (idx >= BATCH * OUTD) return;
    int b = idx / OUTD;
    int o = idx - b * OUTD;
    const float* hb = h + (size_t)b * 64;
    float s = bout[o];
    #pragma unroll
    for (int m = 0; m < 64; ++m)
        s += hb[m] * Wout[m * OUTD + o];
    y[idx] = s;
}

extern "C" void kernel_launch(void* const* d_in, const int* in_sizes, int n_in,
                              void* d_out, int out_size)
{
    (void)in_sizes; (void)n_in; (void)out_size;
    const float* x = (const float*)d_in[0];
    const float *Wi[3], *bi[3], *bl[3], *Wo[3], *bo[3], *Lm[3], *ad[3];
    for (int l = 0; l < 3; ++l) {
        int base = 1 + 7 * l;
        Wi[l] = (const float*)d_in[base + 0];
        bi[l] = (const float*)d_in[base + 1];
        bl[l] = (const float*)d_in[base + 2];
        Wo[l] = (const float*)d_in[base + 3];
        bo[l] = (const float*)d_in[base + 4];
        Lm[l] = (const float*)d_in[base + 5];
        ad[l] = (const float*)d_in[base + 6];
    }
    const float* Wout = (const float*)d_in[22];
    const float* bout = (const float*)d_in[23];

    __half *ah, *wth;
    float *pre, *h;
    cudaGetSymbolAddress((void**)&ah,  g_ah);
    cudaGetSymbolAddress((void**)&wth, g_wth);
    cudaGetSymbolAddress((void**)&pre, g_pre);
    cudaGetSymbolAddress((void**)&h,   g_h);

    cudaFuncSetAttribute(liquid_mma_kernel, cudaFuncAttributeMaxDynamicSharedMemorySize, SM_TOTAL);

    const int Ns[3] = {256, 128, 64};
    const int Ks[3] = {512, 256, 128};
    const size_t woff[3] = {0, 8388608, 10485760};

    for (int l = 0; l < 3; ++l) {
        dim3 g(Ks[l] / 64, Ns[l]);
        wsplit_kernel<<<g, 256>>>(Wi[l], wth + woff[l], Ks[l]);
    }
    xsplit_kernel<<<(BATCH * 512 / 4 + 255) / 256, 256>>>(x, ah, BATCH * 512 / 4);

    for (int l = 0; l < 3; ++l) {
        dim3 grid(BATCH / BM, (Ns[l] * SDIM) / BN);   // = Ns[l]/2
        liquid_mma_kernel<<<grid, 256, SM_TOTAL>>>(ah, wth + woff[l],
                                                   bi[l], bl[l], Wo[l], bo[l], pre,
                                                   Ks[l], Ns[l]);
        lateral_kernel<<<BATCH / 32, 256>>>(pre, Lm[l], ad[l], h, ah, Ns[l]);
    }
    out_kernel<<<(BATCH * OUTD + 255) / 256, 256>>>(h, Wout, bout, (float*)d_out);
}

// round 9
// speedup vs baseline: 5.6543x; 1.0279x over previous
#include <cuda_runtime.h>
#include <cuda_fp16.h>
#include <cstdint>

#define BATCH 4096
#define SDIM  64
#define OUTD  12
#define BM    128     // batch rows per CTA
#define BN    128     // gemm columns per CTA (= 2 neurons)

// ---------------- scratch (device globals; no allocs allowed) ----------------
__device__ __align__(256) __half g_ah[BATCH * 512];    // A fp16 (x or h)
__device__ __align__(256) __half g_wth[11010048];      // W^T fp16, all layers
__device__ __align__(256) float  g_pre[BATCH * 256];
__device__ __align__(256) float  g_h[BATCH * 256];

// ---------------- helpers ----------------
__device__ __forceinline__ uint32_t smem_u32(const void* p) {
    uint32_t a;
    asm("{ .reg .u64 t; cvta.to.shared.u64 t, %1; cvt.u32.u64 %0, t; }" : "=r"(a) : "l"(p));
    return a;
}
__device__ __forceinline__ void cp16(uint32_t s, const void* g) {
    asm volatile("cp.async.cg.shared.global [%0], [%1], 16;" :: "r"(s), "l"(g));
}
#define CP_COMMIT() asm volatile("cp.async.commit_group;" ::: "memory")
#define CP_WAIT(n)  asm volatile("cp.async.wait_group %0;" :: "n"(n) : "memory")

__device__ __forceinline__ void ldm_x4(uint32_t* r, uint32_t addr) {
    asm volatile("ldmatrix.sync.aligned.m8n8.x4.shared.b16 {%0,%1,%2,%3}, [%4];"
                 : "=r"(r[0]), "=r"(r[1]), "=r"(r[2]), "=r"(r[3]) : "r"(addr));
}
__device__ __forceinline__ void mma16816(float* d, const uint32_t* a, const uint32_t* b) {
    asm volatile("mma.sync.aligned.m16n8k16.row.col.f32.f16.f16.f32 "
                 "{%0,%1,%2,%3}, {%4,%5,%6,%7}, {%8,%9}, {%0,%1,%2,%3};"
                 : "+f"(d[0]), "+f"(d[1]), "+f"(d[2]), "+f"(d[3])
                 : "r"(a[0]), "r"(a[1]), "r"(a[2]), "r"(a[3]), "r"(b[0]), "r"(b[1]));
}
__device__ __forceinline__ uint32_t swz(uint32_t off) {   // SW128: rows of 128B
    return off ^ ((off >> 3) & 0x70);
}
// activation: tanh(v) + 0.1*sin(0.5v)*cos(0.3v); tanh.approx MUFU
__device__ __forceinline__ float liquid_act(float v) {
    float t, s, c;
    asm("tanh.approx.f32 %0, %1;" : "=f"(t) : "f"(v));
    asm("sin.approx.f32 %0, %1;" : "=f"(s) : "f"(0.5f * v));
    asm("cos.approx.f32 %0, %1;" : "=f"(c) : "f"(0.3f * v));
    return t + 0.1f * s * c;
}

// smem layout (dynamic): A stages @0/16384/32768 (16KB each);
// B stages @49152/65536/81920; bias @98304 (128 f32); wo @98816 (128 f32)
#define SM_B_OFF   49152
#define SM_BIAS    98304
#define SM_WO      98816
#define SM_TOTAL   99328

// Single-pass fp16 HMMA GEMM + fused activation/output-projection epilogue.
// grid: (BATCH/BM, (N*64)/BN), 128 threads = 4 warps (2 along M x 2 along ncols),
// warp tile 64x64: each warp's 64 columns = one neuron's S dimension.
__global__ void __launch_bounds__(128, 2)
liquid_mma_kernel(const __half* __restrict__ Ah, const __half* __restrict__ Bth,
                  const float* __restrict__ bi, const float* __restrict__ bl,
                  const float* __restrict__ Wo, const float* __restrict__ bo,
                  float* __restrict__ pre, int K, int Nn)
{
    extern __shared__ char smem[];
    const uint32_t sb = smem_u32(smem);
    const int tid = threadIdx.x;
    const int wid  = tid >> 5;
    const int lane = tid & 31;
    const int wm = wid >> 1;          // 0-1: m offset wm*64
    const int wn = wid & 1;           // 0-1: n offset wn*64 (= neuron wn)
    const int b0    = blockIdx.x * BM;
    const int ncol0 = blockIdx.y * BN;

    // bias + wo for this CTA's 128 columns (blockDim == 128)
    {
        int gc = ncol0 + tid;
        int nn = gc >> 6, s = gc & 63;
        ((float*)(smem + SM_BIAS))[tid] = bi[nn * SDIM + s] + bl[nn * SDIM + s];
        ((float*)(smem + SM_WO))[tid]   = Wo[nn * SDIM + s];
    }

    float d[4][8][4];
    #pragma unroll
    for (int mi = 0; mi < 4; ++mi)
        #pragma unroll
        for (int nj = 0; nj < 8; ++nj)
            #pragma unroll
            for (int c = 0; c < 4; ++c) d[mi][nj][c] = 0.f;

    const int niters = K >> 6;

    // per-thread load slots: 8 lines of 16B each for A and B (128 threads)
    const int lrow = tid >> 3;        // 0..15 (+16*i)
    const int lseg = tid & 7;

    // ldmatrix lane address components (identical intra-warp pattern to validated R5)
    const int a_row = wm * 64 + (lane & 15);
    const int a_cb  = (lane >> 4) * 16;
    const int b_row = wn * 64 + (lane & 7) + ((lane >> 4) << 3);
    const int b_cb  = ((lane >> 3) & 1) * 16;

    auto issue_loads = [&](int it, int st) {
        const int k0 = it << 6;
        uint32_t sA = sb + st * 16384;
        uint32_t sB = sb + SM_B_OFF + st * 16384;
        #pragma unroll
        for (int i = 0; i < 8; ++i) {
            int row = lrow + i * 16;
            uint32_t so = swz(row * 128 + lseg * 16);
            cp16(sA + so, Ah  + (size_t)(b0 + row) * K + k0 + lseg * 8);
            cp16(sB + so, Bth + (size_t)(ncol0 + row) * K + k0 + lseg * 8);
        }
        CP_COMMIT();
    };

    issue_loads(0, 0);
    if (niters > 1) issue_loads(1, 1);

    int cur = 0;
    for (int it = 0; it < niters; ++it) {
        if (it == niters - 1) { CP_WAIT(0); } else { CP_WAIT(1); }
        __syncthreads();
        if (it + 2 < niters) {
            int nx = cur + 2; if (nx >= 3) nx -= 3;
            issue_loads(it + 2, nx);
        }

        uint32_t sA = sb + cur * 16384;
        uint32_t sB = sb + SM_B_OFF + cur * 16384;
        #pragma unroll
        for (int ks = 0; ks < 4; ++ks) {
            uint32_t afr[4][4], bfr[4][4];
            #pragma unroll
            for (int mi = 0; mi < 4; ++mi)
                ldm_x4(afr[mi], sA + swz((a_row + mi * 16) * 128 + ks * 32 + a_cb));
            #pragma unroll
            for (int nj2 = 0; nj2 < 4; ++nj2)
                ldm_x4(bfr[nj2], sB + swz((b_row + nj2 * 16) * 128 + ks * 32 + b_cb));
            #pragma unroll
            for (int mi = 0; mi < 4; ++mi)
                #pragma unroll
                for (int nj = 0; nj < 8; ++nj)
                    mma16816(d[mi][nj], afr[mi], &bfr[nj >> 1][(nj & 1) * 2]);
        }
        cur = (cur == 2) ? 0 : cur + 1;
    }

    // ---- epilogue: act + Wo dot; warp's 64 cols == one neuron, fully in-warp ----
    {
        const int g = lane >> 2, i = lane & 3;
        const float* bs = (const float*)(smem + SM_BIAS) + wn * 64;
        const float* ws = (const float*)(smem + SM_WO)   + wn * 64;
        const int neuron = blockIdx.y * 2 + wn;
        const float bon = bo[neuron];

        #pragma unroll
        for (int mi = 0; mi < 4; ++mi) {
            float p0 = 0.f, p1 = 0.f;
            #pragma unroll
            for (int nj = 0; nj < 8; ++nj) {
                int c = nj * 8 + 2 * i;
                float w0 = ws[c], w1 = ws[c + 1];
                float bb0 = bs[c], bb1 = bs[c + 1];
                p0 += liquid_act(d[mi][nj][0] + bb0) * w0 + liquid_act(d[mi][nj][1] + bb1) * w1;
                p1 += liquid_act(d[mi][nj][2] + bb0) * w0 + liquid_act(d[mi][nj][3] + bb1) * w1;
            }
            p0 += __shfl_xor_sync(0xffffffffu, p0, 1);
            p0 += __shfl_xor_sync(0xffffffffu, p0, 2);
            p1 += __shfl_xor_sync(0xffffffffu, p1, 1);
            p1 += __shfl_xor_sync(0xffffffffu, p1, 2);
            if (i == 0) {
                int r = b0 + wm * 64 + mi * 16 + g;
                pre[(size_t)r * Nn + neuron]       = p0 + bon;
                pre[(size_t)(r + 8) * Nn + neuron] = p1 + bon;
            }
        }
    }
}

// ---------------- weight transpose to fp16: Wi[n][k][s] -> Wt[n*64+s][k] ----------------
__global__ __launch_bounds__(256)
void wsplit_kernel(const float* __restrict__ Wi, __half* __restrict__ Wth, int K)
{
    const int n  = blockIdx.y;
    const int k0 = blockIdx.x * 64;
    __shared__ float tile[64][65];
    const float* src = Wi + ((size_t)n * K + k0) * SDIM;
    for (int i = threadIdx.x; i < 4096; i += 256) {
        int kk = i >> 6, s = i & 63;
        tile[kk][s] = src[kk * SDIM + s];
    }
    __syncthreads();
    for (int i = threadIdx.x; i < 4096; i += 256) {
        int s = i >> 6, kk = i & 63;
        Wth[(size_t)n * SDIM * K + (size_t)s * K + k0 + kk] = __float2half(tile[kk][s]);
    }
}

// ---------------- x -> fp16 (vectorized, 4 elems/thread) ----------------
__global__ __launch_bounds__(256)
void xsplit_kernel(const float* __restrict__ x, __half* __restrict__ xh, int n4)
{
    int i = blockIdx.x * 256 + threadIdx.x;
    if (i >= n4) return;
    float4 v = ((const float4*)x)[i];
    __half2 lo = __floats2half2_rn(v.x, v.y);
    __half2 hi = __floats2half2_rn(v.z, v.w);
    ((__half2*)xh)[2 * i]     = lo;
    ((__half2*)xh)[2 * i + 1] = hi;
}

// ---------------- lateral mixing (f32x2 pairs); also emits fp16 for next layer ----------------
__global__ __launch_bounds__(256)
void lateral_kernel(const float* __restrict__ pre, const float* __restrict__ L,
                    const float* __restrict__ a, float* __restrict__ h,
                    __half* __restrict__ hh, int N)
{
    const int b0  = blockIdx.x * 32;
    const int tid = threadIdx.x;
    __shared__ float ps[32 * 256];

    for (int idx = tid; idx < 32 * N; idx += 256)
        ps[idx] = pre[(size_t)(b0 + idx / N) * N + (idx % N)];
    __syncthreads();

    const int half = N >> 1;
    for (int it = tid; it < 32 * half; it += 256) {
        int r  = it / half;
        int np = it - r * half;
        int n  = np * 2;
        const float* pr = ps + r * N;
        unsigned long long acc = 0ull;
        #pragma unroll 4
        for (int m = 0; m < N; ++m) {
            unsigned long long lp = *(const unsigned long long*)(L + (size_t)m * N + n);
            unsigned long long ap;
            asm("mov.b64 %0, {%1, %1};" : "=l"(ap) : "r"(__float_as_uint(pr[m])));
            asm("fma.rn.f32x2 %0, %1, %2, %0;" : "+l"(acc) : "l"(ap), "l"(lp));
        }
        float s0 = __uint_as_float((unsigned)(acc & 0xffffffffull));
        float s1 = __uint_as_float((unsigned)(acc >> 32));
        float v0 = (pr[n]     + 0.1f * s0) * a[n];
        float v1 = (pr[n + 1] + 0.1f * s1) * a[n + 1];
        size_t o = (size_t)(b0 + r) * N + n;
        h[o] = v0; h[o + 1] = v1;
        hh[o] = __float2half(v0); hh[o + 1] = __float2half(v1);
    }
}

// ---------------- final projection ----------------
__global__ __launch_bounds__(256)
void out_kernel(const float* __restrict__ h, const float* __restrict__ Wout,
                const float* __restrict__ bout, float* __restrict__ y)
{
    int idx = blockIdx.x * blockDim.x + threadIdx.x;
    if (idx >= BATCH * OUTD) return;
    int b = idx / OUTD;
    int o = idx - b * OUTD;
    const float* hb = h + (size_t)b * 64;
    float s = bout[o];
    #pragma unroll
    for (int m = 0; m < 64; ++m)
        s += hb[m] * Wout[m * OUTD + o];
    y[idx] = s;
}

extern "C" void kernel_launch(void* const* d_in, const int* in_sizes, int n_in,
                              void* d_out, int out_size)
{
    (void)in_sizes; (void)n_in; (void)out_size;
    const float* x = (const float*)d_in[0];
    const float *Wi[3], *bi[3], *bl[3], *Wo[3], *bo[3], *Lm[3], *ad[3];
    for (int l = 0; l < 3; ++l) {
        int base = 1 + 7 * l;
        Wi[l] = (const float*)d_in[base + 0];
        bi[l] = (const float*)d_in[base + 1];
        bl[l] = (const float*)d_in[base + 2];
        Wo[l] = (const float*)d_in[base + 3];
        bo[l] = (const float*)d_in[base + 4];
        Lm[l] = (const float*)d_in[base + 5];
        ad[l] = (const float*)d_in[base + 6];
    }
    const float* Wout = (const float*)d_in[22];
    const float* bout = (const float*)d_in[23];

    __half *ah, *wth;
    float *pre, *h;
    cudaGetSymbolAddress((void**)&ah,  g_ah);
    cudaGetSymbolAddress((void**)&wth, g_wth);
    cudaGetSymbolAddress((void**)&pre, g_pre);
    cudaGetSymbolAddress((void**)&h,   g_h);

    cudaFuncSetAttribute(liquid_mma_kernel, cudaFuncAttributeMaxDynamicSharedMemorySize, SM_TOTAL);

    const int Ns[3] = {256, 128, 64};
    const int Ks[3] = {512, 256, 128};
    const size_t woff[3] = {0, 8388608, 10485760};

    for (int l = 0; l < 3; ++l) {
        dim3 g(Ks[l] / 64, Ns[l]);
        wsplit_kernel<<<g, 256>>>(Wi[l], wth + woff[l], Ks[l]);
    }
    xsplit_kernel<<<(BATCH * 512 / 4 + 255) / 256, 256>>>(x, ah, BATCH * 512 / 4);

    for (int l = 0; l < 3; ++l) {
        dim3 grid(BATCH / BM, (Ns[l] * SDIM) / BN);   // = Ns[l]/2
        liquid_mma_kernel<<<grid, 128, SM_TOTAL>>>(ah, wth + woff[l],
                                                   bi[l], bl[l], Wo[l], bo[l], pre,
                                                   Ks[l], Ns[l]);
        lateral_kernel<<<BATCH / 32, 256>>>(pre, Lm[l], ad[l], h, ah, Ns[l]);
    }
    out_kernel<<<(BATCH * OUTD + 255) / 256, 256>>>(h, Wout, bout, (float*)d_out);
}

// round 10
// speedup vs baseline: 6.0771x; 1.0748x over previous
#include <cuda_runtime.h>
#include <cuda_fp16.h>
#include <cstdint>

#define BATCH 4096
#define SDIM  64
#define OUTD  12
#define BM    128     // batch rows per CTA
#define BN    128     // gemm columns per CTA (= 2 neurons)

// ---------------- scratch (device globals; no allocs allowed) ----------------
__device__ __align__(256) __half g_ah[BATCH * 512];    // A fp16 (x or h)
__device__ __align__(256) __half g_wth[11010048];      // W^T fp16, all layers
__device__ __align__(256) float  g_pre[BATCH * 256];
__device__ __align__(256) float  g_h[BATCH * 256];

// ---------------- helpers ----------------
__device__ __forceinline__ uint32_t smem_u32(const void* p) {
    uint32_t a;
    asm("{ .reg .u64 t; cvta.to.shared.u64 t, %1; cvt.u32.u64 %0, t; }" : "=r"(a) : "l"(p));
    return a;
}
__device__ __forceinline__ void cp16(uint32_t s, const void* g) {
    asm volatile("cp.async.cg.shared.global [%0], [%1], 16;" :: "r"(s), "l"(g));
}
#define CP_COMMIT() asm volatile("cp.async.commit_group;" ::: "memory")
#define CP_WAIT(n)  asm volatile("cp.async.wait_group %0;" :: "n"(n) : "memory")

__device__ __forceinline__ void ldm_x4(uint32_t* r, uint32_t addr) {
    asm volatile("ldmatrix.sync.aligned.m8n8.x4.shared.b16 {%0,%1,%2,%3}, [%4];"
                 : "=r"(r[0]), "=r"(r[1]), "=r"(r[2]), "=r"(r[3]) : "r"(addr));
}
__device__ __forceinline__ void mma16816(float* d, const uint32_t* a, const uint32_t* b) {
    asm volatile("mma.sync.aligned.m16n8k16.row.col.f32.f16.f16.f32 "
                 "{%0,%1,%2,%3}, {%4,%5,%6,%7}, {%8,%9}, {%0,%1,%2,%3};"
                 : "+f"(d[0]), "+f"(d[1]), "+f"(d[2]), "+f"(d[3])
                 : "r"(a[0]), "r"(a[1]), "r"(a[2]), "r"(a[3]), "r"(b[0]), "r"(b[1]));
}
__device__ __forceinline__ uint32_t swz(uint32_t off) {   // SW128: rows of 128B
    return off ^ ((off >> 3) & 0x70);
}
// activation: tanh(v) + 0.1*sin(0.5v)*cos(0.3v); tanh.approx MUFU
__device__ __forceinline__ float liquid_act(float v) {
    float t, s, c;
    asm("tanh.approx.f32 %0, %1;" : "=f"(t) : "f"(v));
    asm("sin.approx.f32 %0, %1;" : "=f"(s) : "f"(0.5f * v));
    asm("cos.approx.f32 %0, %1;" : "=f"(c) : "f"(0.3f * v));
    return t + 0.1f * s * c;
}

// smem layout (dynamic): A stages @0/16384/32768 (16KB each);
// B stages @49152/65536/81920; bias @98304 (128 f32); wo @98816 (128 f32)
#define SM_B_OFF   49152
#define SM_BIAS    98304
#define SM_WO      98816
#define SM_TOTAL   99328

// Single-pass fp16 HMMA GEMM + fused activation/output-projection epilogue.
// grid: (BATCH/BM, (N*64)/BN), 128 threads = 4 warps (2 along M x 2 along ncols),
// warp tile 64x64: each warp's 64 columns = one neuron's S dimension.
__global__ void __launch_bounds__(128, 2)
liquid_mma_kernel(const __half* __restrict__ Ah, const __half* __restrict__ Bth,
                  const float* __restrict__ bi, const float* __restrict__ bl,
                  const float* __restrict__ Wo, const float* __restrict__ bo,
                  float* __restrict__ pre, int K, int Nn)
{
    extern __shared__ char smem[];
    const uint32_t sb = smem_u32(smem);
    const int tid = threadIdx.x;
    const int wid  = tid >> 5;
    const int lane = tid & 31;
    const int wm = wid >> 1;          // 0-1: m offset wm*64
    const int wn = wid & 1;           // 0-1: n offset wn*64 (= neuron wn)
    const int b0    = blockIdx.x * BM;
    const int ncol0 = blockIdx.y * BN;

    // bias + wo for this CTA's 128 columns (blockDim == 128)
    {
        int gc = ncol0 + tid;
        int nn = gc >> 6, s = gc & 63;
        ((float*)(smem + SM_BIAS))[tid] = bi[nn * SDIM + s] + bl[nn * SDIM + s];
        ((float*)(smem + SM_WO))[tid]   = Wo[nn * SDIM + s];
    }

    float d[4][8][4];
    #pragma unroll
    for (int mi = 0; mi < 4; ++mi)
        #pragma unroll
        for (int nj = 0; nj < 8; ++nj)
            #pragma unroll
            for (int c = 0; c < 4; ++c) d[mi][nj][c] = 0.f;

    const int niters = K >> 6;

    // per-thread load slots: 8 lines of 16B each for A and B (128 threads)
    const int lrow = tid >> 3;        // 0..15 (+16*i)
    const int lseg = tid & 7;

    // ldmatrix lane address components
    const int a_row = wm * 64 + (lane & 15);
    const int a_cb  = (lane >> 4) * 16;
    const int b_row = wn * 64 + (lane & 7) + ((lane >> 4) << 3);
    const int b_cb  = ((lane >> 3) & 1) * 16;

    auto issue_loads = [&](int it, int st) {
        const int k0 = it << 6;
        uint32_t sA = sb + st * 16384;
        uint32_t sB = sb + SM_B_OFF + st * 16384;
        #pragma unroll
        for (int i = 0; i < 8; ++i) {
            int row = lrow + i * 16;
            uint32_t so = swz(row * 128 + lseg * 16);
            cp16(sA + so, Ah  + (size_t)(b0 + row) * K + k0 + lseg * 8);
            cp16(sB + so, Bth + (size_t)(ncol0 + row) * K + k0 + lseg * 8);
        }
        CP_COMMIT();
    };

    issue_loads(0, 0);
    if (niters > 1) issue_loads(1, 1);

    int cur = 0;
    for (int it = 0; it < niters; ++it) {
        if (it == niters - 1) { CP_WAIT(0); } else { CP_WAIT(1); }
        __syncthreads();
        if (it + 2 < niters) {
            int nx = cur + 2; if (nx >= 3) nx -= 3;
            issue_loads(it + 2, nx);
        }

        uint32_t sA = sb + cur * 16384;
        uint32_t sB = sb + SM_B_OFF + cur * 16384;
        #pragma unroll
        for (int ks = 0; ks < 4; ++ks) {
            uint32_t afr[4][4], bfr[4][4];
            #pragma unroll
            for (int mi = 0; mi < 4; ++mi)
                ldm_x4(afr[mi], sA + swz((a_row + mi * 16) * 128 + ks * 32 + a_cb));
            #pragma unroll
            for (int nj2 = 0; nj2 < 4; ++nj2)
                ldm_x4(bfr[nj2], sB + swz((b_row + nj2 * 16) * 128 + ks * 32 + b_cb));
            #pragma unroll
            for (int mi = 0; mi < 4; ++mi)
                #pragma unroll
                for (int nj = 0; nj < 8; ++nj)
                    mma16816(d[mi][nj], afr[mi], &bfr[nj >> 1][(nj & 1) * 2]);
        }
        cur = (cur == 2) ? 0 : cur + 1;
    }

    // ---- epilogue: act + Wo dot; warp's 64 cols == one neuron, fully in-warp ----
    {
        const int g = lane >> 2, i = lane & 3;
        const float* bs = (const float*)(smem + SM_BIAS) + wn * 64;
        const float* ws = (const float*)(smem + SM_WO)   + wn * 64;
        const int neuron = blockIdx.y * 2 + wn;
        const float bon = bo[neuron];

        #pragma unroll
        for (int mi = 0; mi < 4; ++mi) {
            float p0 = 0.f, p1 = 0.f;
            #pragma unroll
            for (int nj = 0; nj < 8; ++nj) {
                int c = nj * 8 + 2 * i;
                float w0 = ws[c], w1 = ws[c + 1];
                float bb0 = bs[c], bb1 = bs[c + 1];
                p0 += liquid_act(d[mi][nj][0] + bb0) * w0 + liquid_act(d[mi][nj][1] + bb1) * w1;
                p1 += liquid_act(d[mi][nj][2] + bb0) * w0 + liquid_act(d[mi][nj][3] + bb1) * w1;
            }
            p0 += __shfl_xor_sync(0xffffffffu, p0, 1);
            p0 += __shfl_xor_sync(0xffffffffu, p0, 2);
            p1 += __shfl_xor_sync(0xffffffffu, p1, 1);
            p1 += __shfl_xor_sync(0xffffffffu, p1, 2);
            if (i == 0) {
                int r = b0 + wm * 64 + mi * 16 + g;
                pre[(size_t)r * Nn + neuron]       = p0 + bon;
                pre[(size_t)(r + 8) * Nn + neuron] = p1 + bon;
            }
        }
    }
}

// ---------------- merged weight transpose (all 3 layers, one launch) ----------------
// Wi[n][k][s] -> Wt[n*64+s][k]; 2688 linear blocks.
__global__ __launch_bounds__(256)
void wsplit_all_kernel(const float* __restrict__ Wi0, const float* __restrict__ Wi1,
                       const float* __restrict__ Wi2, __half* __restrict__ wth)
{
    int b = blockIdx.x;
    const float* Wi; __half* dst; int K, n, kc;
    if (b < 2048)      { Wi = Wi0; dst = wth;            K = 512; kc = b & 7; n = b >> 3; }
    else if (b < 2560) { b -= 2048; Wi = Wi1; dst = wth + 8388608;  K = 256; kc = b & 3; n = b >> 2; }
    else               { b -= 2560; Wi = Wi2; dst = wth + 10485760; K = 128; kc = b & 1; n = b >> 1; }
    const int k0 = kc * 64;

    __shared__ float tile[64][65];
    const float* src = Wi + ((size_t)n * K + k0) * SDIM;
    for (int i = threadIdx.x; i < 4096; i += 256) {
        int kk = i >> 6, s = i & 63;
        tile[kk][s] = src[kk * SDIM + s];
    }
    __syncthreads();
    for (int i = threadIdx.x; i < 4096; i += 256) {
        int s = i >> 6, kk = i & 63;
        dst[(size_t)n * SDIM * K + (size_t)s * K + k0 + kk] = __float2half(tile[kk][s]);
    }
}

// ---------------- x -> fp16 (vectorized, 4 elems/thread) ----------------
__global__ __launch_bounds__(256)
void xsplit_kernel(const float* __restrict__ x, __half* __restrict__ xh, int n4)
{
    int i = blockIdx.x * 256 + threadIdx.x;
    if (i >= n4) return;
    float4 v = ((const float4*)x)[i];
    __half2 lo = __floats2half2_rn(v.x, v.y);
    __half2 hi = __floats2half2_rn(v.z, v.w);
    ((__half2*)xh)[2 * i]     = lo;
    ((__half2*)xh)[2 * i + 1] = hi;
}

// ---------------- lateral v3: smem-tiled, f32x2, column-split grid ----------------
// grid (BATCH/32, N/64), 256 threads. Block: 32 batch rows x 64 output cols.
// smem: ps[32][N] (pre rows) + Ls[N][64] (L column slab). Thread: 2 rows x 4 cols.
__global__ __launch_bounds__(256)
void lateral_kernel(const float* __restrict__ pre, const float* __restrict__ L,
                    const float* __restrict__ a, float* __restrict__ h,
                    __half* __restrict__ hh, int N)
{
    extern __shared__ float lsm[];
    float* ps = lsm;              // 32*N
    float* Ls = lsm + 32 * N;     // N*64
    const int b0  = blockIdx.x * 32;
    const int c0  = blockIdx.y * 64;
    const int tid = threadIdx.x;

    for (int idx = tid; idx < 32 * N; idx += 256)
        ps[idx] = pre[(size_t)(b0 + idx / N) * N + (idx % N)];
    for (int idx = tid; idx < N * 64; idx += 256)
        Ls[idx] = L[(size_t)(idx >> 6) * N + c0 + (idx & 63)];
    __syncthreads();

    const int tr = tid >> 4;          // 0..15 -> rows 2tr, 2tr+1
    const int tc = tid & 15;          // cols 4*tc
    const int r0 = 2 * tr;
    const float* pr0 = ps + (size_t)r0 * N;
    const float* pr1 = pr0 + N;

    unsigned long long acc00 = 0, acc01 = 0, acc10 = 0, acc11 = 0;
    #pragma unroll 4
    for (int m = 0; m < N; ++m) {
        ulonglong2 lv = *(const ulonglong2*)(Ls + m * 64 + 4 * tc);
        unsigned long long a0, a1;
        asm("mov.b64 %0, {%1, %1};" : "=l"(a0) : "r"(__float_as_uint(pr0[m])));
        asm("mov.b64 %0, {%1, %1};" : "=l"(a1) : "r"(__float_as_uint(pr1[m])));
        asm("fma.rn.f32x2 %0, %1, %2, %0;" : "+l"(acc00) : "l"(a0), "l"(lv.x));
        asm("fma.rn.f32x2 %0, %1, %2, %0;" : "+l"(acc01) : "l"(a0), "l"(lv.y));
        asm("fma.rn.f32x2 %0, %1, %2, %0;" : "+l"(acc10) : "l"(a1), "l"(lv.x));
        asm("fma.rn.f32x2 %0, %1, %2, %0;" : "+l"(acc11) : "l"(a1), "l"(lv.y));
    }

    const int n0 = c0 + 4 * tc;
    float4 av = *(const float4*)(a + n0);

    #pragma unroll
    for (int rr = 0; rr < 2; ++rr) {
        unsigned long long aclo = rr ? acc10 : acc00;
        unsigned long long achi = rr ? acc11 : acc01;
        const float* pr = rr ? pr1 : pr0;
        float s0 = __uint_as_float((unsigned)(aclo & 0xffffffffull));
        float s1 = __uint_as_float((unsigned)(aclo >> 32));
        float s2 = __uint_as_float((unsigned)(achi & 0xffffffffull));
        float s3 = __uint_as_float((unsigned)(achi >> 32));
        float v0 = (pr[n0]     + 0.1f * s0) * av.x;
        float v1 = (pr[n0 + 1] + 0.1f * s1) * av.y;
        float v2 = (pr[n0 + 2] + 0.1f * s2) * av.z;
        float v3 = (pr[n0 + 3] + 0.1f * s3) * av.w;
        size_t o = (size_t)(b0 + r0 + rr) * N + n0;
        *(float4*)(h + o) = make_float4(v0, v1, v2, v3);
        ((__half2*)(hh + o))[0] = __floats2half2_rn(v0, v1);
        ((__half2*)(hh + o))[1] = __floats2half2_rn(v2, v3);
    }
}

// ---------------- final projection ----------------
__global__ __launch_bounds__(256)
void out_kernel(const float* __restrict__ h, const float* __restrict__ Wout,
                const float* __restrict__ bout, float* __restrict__ y)
{
    int idx = blockIdx.x * blockDim.x + threadIdx.x;
    if (idx >= BATCH * OUTD) return;
    int b = idx / OUTD;
    int o = idx - b * OUTD;
    const float* hb = h + (size_t)b * 64;
    float s = bout[o];
    #pragma unroll
    for (int m = 0; m < 64; ++m)
        s += hb[m] * Wout[m * OUTD + o];
    y[idx] = s;
}

extern "C" void kernel_launch(void* const* d_in, const int* in_sizes, int n_in,
                              void* d_out, int out_size)
{
    (void)in_sizes; (void)n_in; (void)out_size;
    const float* x = (const float*)d_in[0];
    const float *Wi[3], *bi[3], *bl[3], *Wo[3], *bo[3], *Lm[3], *ad[3];
    for (int l = 0; l < 3; ++l) {
        int base = 1 + 7 * l;
        Wi[l] = (const float*)d_in[base + 0];
        bi[l] = (const float*)d_in[base + 1];
        bl[l] = (const float*)d_in[base + 2];
        Wo[l] = (const float*)d_in[base + 3];
        bo[l] = (const float*)d_in[base + 4];
        Lm[l] = (const float*)d_in[base + 5];
        ad[l] = (const float*)d_in[base + 6];
    }
    const float* Wout = (const float*)d_in[22];
    const float* bout = (const float*)d_in[23];

    __half *ah, *wth;
    float *pre, *h;
    cudaGetSymbolAddress((void**)&ah,  g_ah);
    cudaGetSymbolAddress((void**)&wth, g_wth);
    cudaGetSymbolAddress((void**)&pre, g_pre);
    cudaGetSymbolAddress((void**)&h,   g_h);

    cudaFuncSetAttribute(liquid_mma_kernel, cudaFuncAttributeMaxDynamicSharedMemorySize, SM_TOTAL);
    cudaFuncSetAttribute(lateral_kernel, cudaFuncAttributeMaxDynamicSharedMemorySize, 98304);

    const int Ns[3] = {256, 128, 64};
    const int Ks[3] = {512, 256, 128};
    const size_t woff[3] = {0, 8388608, 10485760};

    wsplit_all_kernel<<<2688, 256>>>(Wi[0], Wi[1], Wi[2], wth);
    xsplit_kernel<<<(BATCH * 512 / 4 + 255) / 256, 256>>>(x, ah, BATCH * 512 / 4);

    for (int l = 0; l < 3; ++l) {
        dim3 grid(BATCH / BM, (Ns[l] * SDIM) / BN);   // = Ns[l]/2
        liquid_mma_kernel<<<grid, 128, SM_TOTAL>>>(ah, wth + woff[l],
                                                   bi[l], bl[l], Wo[l], bo[l], pre,
                                                   Ks[l], Ns[l]);
        dim3 lgrid(BATCH / 32, Ns[l] / 64);
        int lsmem = (32 * Ns[l] + Ns[l] * 64) * 4;
        lateral_kernel<<<lgrid, 256, lsmem>>>(pre, Lm[l], ad[l], h, ah, Ns[l]);
    }
    out_kernel<<<(BATCH * OUTD + 255) / 256, 256>>>(h, Wout, bout, (float*)d_out);
}

// round 11
// speedup vs baseline: 10.6070x; 1.7454x over previous
#include <cuda_runtime.h>
#include <cuda_fp16.h>
#include <cstdint>

#define BATCH 4096
#define SDIM  64
#define OUTD  12
#define BM    128     // batch rows per CTA
#define BN    128     // gemm columns per CTA (= 2 neurons)

// ---------------- scratch (device globals; no allocs allowed) ----------------
__device__ __align__(256) __half g_ah[BATCH * 512];    // A fp16 (x or h)
__device__ __align__(256) __half g_wth[11010048];      // W^T fp16, all layers
__device__ __align__(256) __half g_preh[BATCH * 256];  // pre (fp16)
__device__ __align__(256) __half g_lat[86016];         // La^T fp16, all layers
__device__ __align__(256) float  g_h[BATCH * 256];

// ---------------- helpers ----------------
__device__ __forceinline__ uint32_t smem_u32(const void* p) {
    uint32_t a;
    asm("{ .reg .u64 t; cvta.to.shared.u64 t, %1; cvt.u32.u64 %0, t; }" : "=r"(a) : "l"(p));
    return a;
}
__device__ __forceinline__ void cp16(uint32_t s, const void* g) {
    asm volatile("cp.async.cg.shared.global [%0], [%1], 16;" :: "r"(s), "l"(g));
}
#define CP_COMMIT() asm volatile("cp.async.commit_group;" ::: "memory")
#define CP_WAIT(n)  asm volatile("cp.async.wait_group %0;" :: "n"(n) : "memory")

__device__ __forceinline__ void ldm_x4(uint32_t* r, uint32_t addr) {
    asm volatile("ldmatrix.sync.aligned.m8n8.x4.shared.b16 {%0,%1,%2,%3}, [%4];"
                 : "=r"(r[0]), "=r"(r[1]), "=r"(r[2]), "=r"(r[3]) : "r"(addr));
}
__device__ __forceinline__ void mma16816(float* d, const uint32_t* a, const uint32_t* b) {
    asm volatile("mma.sync.aligned.m16n8k16.row.col.f32.f16.f16.f32 "
                 "{%0,%1,%2,%3}, {%4,%5,%6,%7}, {%8,%9}, {%0,%1,%2,%3};"
                 : "+f"(d[0]), "+f"(d[1]), "+f"(d[2]), "+f"(d[3])
                 : "r"(a[0]), "r"(a[1]), "r"(a[2]), "r"(a[3]), "r"(b[0]), "r"(b[1]));
}
__device__ __forceinline__ uint32_t swz(uint32_t off) {   // SW128: rows of 128B
    return off ^ ((off >> 3) & 0x70);
}
// activation: tanh(v) + 0.1*sin(0.5v)*cos(0.3v); tanh.approx MUFU
__device__ __forceinline__ float liquid_act(float v) {
    float t, s, c;
    asm("tanh.approx.f32 %0, %1;" : "=f"(t) : "f"(v));
    asm("sin.approx.f32 %0, %1;" : "=f"(s) : "f"(0.5f * v));
    asm("cos.approx.f32 %0, %1;" : "=f"(c) : "f"(0.3f * v));
    return t + 0.1f * s * c;
}

// smem layout main gemm: A stages @0/16384/32768; B stages @49152/65536/81920;
// bias @98304 (128 f32); wo @98816 (128 f32)
#define SM_B_OFF   49152
#define SM_BIAS    98304
#define SM_WO      98816
#define SM_TOTAL   99328

// Single-pass fp16 HMMA GEMM + fused activation/output-projection epilogue.
// grid: (BATCH/BM, (N*64)/BN), 128 threads = 4 warps, warp tile 64x64.
__global__ void __launch_bounds__(128, 2)
liquid_mma_kernel(const __half* __restrict__ Ah, const __half* __restrict__ Bth,
                  const float* __restrict__ bi, const float* __restrict__ bl,
                  const float* __restrict__ Wo, const float* __restrict__ bo,
                  __half* __restrict__ preh, int K, int Nn)
{
    extern __shared__ char smem[];
    const uint32_t sb = smem_u32(smem);
    const int tid = threadIdx.x;
    const int wid  = tid >> 5;
    const int lane = tid & 31;
    const int wm = wid >> 1;
    const int wn = wid & 1;
    const int b0    = blockIdx.x * BM;
    const int ncol0 = blockIdx.y * BN;

    {
        int gc = ncol0 + tid;
        int nn = gc >> 6, s = gc & 63;
        ((float*)(smem + SM_BIAS))[tid] = bi[nn * SDIM + s] + bl[nn * SDIM + s];
        ((float*)(smem + SM_WO))[tid]   = Wo[nn * SDIM + s];
    }

    float d[4][8][4];
    #pragma unroll
    for (int mi = 0; mi < 4; ++mi)
        #pragma unroll
        for (int nj = 0; nj < 8; ++nj)
            #pragma unroll
            for (int c = 0; c < 4; ++c) d[mi][nj][c] = 0.f;

    const int niters = K >> 6;
    const int lrow = tid >> 3;
    const int lseg = tid & 7;
    const int a_row = wm * 64 + (lane & 15);
    const int a_cb  = (lane >> 4) * 16;
    const int b_row = wn * 64 + (lane & 7) + ((lane >> 4) << 3);
    const int b_cb  = ((lane >> 3) & 1) * 16;

    auto issue_loads = [&](int it, int st) {
        const int k0 = it << 6;
        uint32_t sA = sb + st * 16384;
        uint32_t sB = sb + SM_B_OFF + st * 16384;
        #pragma unroll
        for (int i = 0; i < 8; ++i) {
            int row = lrow + i * 16;
            uint32_t so = swz(row * 128 + lseg * 16);
            cp16(sA + so, Ah  + (size_t)(b0 + row) * K + k0 + lseg * 8);
            cp16(sB + so, Bth + (size_t)(ncol0 + row) * K + k0 + lseg * 8);
        }
        CP_COMMIT();
    };

    issue_loads(0, 0);
    if (niters > 1) issue_loads(1, 1);

    int cur = 0;
    for (int it = 0; it < niters; ++it) {
        if (it == niters - 1) { CP_WAIT(0); } else { CP_WAIT(1); }
        __syncthreads();
        if (it + 2 < niters) {
            int nx = cur + 2; if (nx >= 3) nx -= 3;
            issue_loads(it + 2, nx);
        }

        uint32_t sA = sb + cur * 16384;
        uint32_t sB = sb + SM_B_OFF + cur * 16384;
        #pragma unroll
        for (int ks = 0; ks < 4; ++ks) {
            uint32_t afr[4][4], bfr[4][4];
            #pragma unroll
            for (int mi = 0; mi < 4; ++mi)
                ldm_x4(afr[mi], sA + swz((a_row + mi * 16) * 128 + ks * 32 + a_cb));
            #pragma unroll
            for (int nj2 = 0; nj2 < 4; ++nj2)
                ldm_x4(bfr[nj2], sB + swz((b_row + nj2 * 16) * 128 + ks * 32 + b_cb));
            #pragma unroll
            for (int mi = 0; mi < 4; ++mi)
                #pragma unroll
                for (int nj = 0; nj < 8; ++nj)
                    mma16816(d[mi][nj], afr[mi], &bfr[nj >> 1][(nj & 1) * 2]);
        }
        cur = (cur == 2) ? 0 : cur + 1;
    }

    // ---- epilogue: act + Wo dot; writes pre in fp16 ----
    {
        const int g = lane >> 2, i = lane & 3;
        const float* bs = (const float*)(smem + SM_BIAS) + wn * 64;
        const float* ws = (const float*)(smem + SM_WO)   + wn * 64;
        const int neuron = blockIdx.y * 2 + wn;
        const float bon = bo[neuron];

        #pragma unroll
        for (int mi = 0; mi < 4; ++mi) {
            float p0 = 0.f, p1 = 0.f;
            #pragma unroll
            for (int nj = 0; nj < 8; ++nj) {
                int c = nj * 8 + 2 * i;
                float w0 = ws[c], w1 = ws[c + 1];
                float bb0 = bs[c], bb1 = bs[c + 1];
                p0 += liquid_act(d[mi][nj][0] + bb0) * w0 + liquid_act(d[mi][nj][1] + bb1) * w1;
                p1 += liquid_act(d[mi][nj][2] + bb0) * w0 + liquid_act(d[mi][nj][3] + bb1) * w1;
            }
            p0 += __shfl_xor_sync(0xffffffffu, p0, 1);
            p0 += __shfl_xor_sync(0xffffffffu, p0, 2);
            p1 += __shfl_xor_sync(0xffffffffu, p1, 1);
            p1 += __shfl_xor_sync(0xffffffffu, p1, 2);
            if (i == 0) {
                int r = b0 + wm * 64 + mi * 16 + g;
                preh[(size_t)r * Nn + neuron]       = __float2half(p0 + bon);
                preh[(size_t)(r + 8) * Nn + neuron] = __float2half(p1 + bon);
            }
        }
    }
}

// ---------------- lateral GEMM: h[b][n] = sum_m preh[b][m] * La[m][n] ----------------
// B operand: Lat[n][k] = (d_kn + 0.1 L[k][n]) * a[n], fp16, K=N contiguous.
// grid (BATCH/128, N/64), 128 threads = 4 warps, warp tile 64x32.
// smem: A stages @0 (16KB x3), B stages @49152 (8KB x3) = 73728.
#define LSM_B_OFF 49152
#define LSM_TOTAL 73728
__global__ void __launch_bounds__(128, 2)
lat_mma_kernel(const __half* __restrict__ preh, const __half* __restrict__ Lat,
               float* __restrict__ h, __half* __restrict__ hh, int N)
{
    extern __shared__ char smem[];
    const uint32_t sb = smem_u32(smem);
    const int tid = threadIdx.x;
    const int wid  = tid >> 5;
    const int lane = tid & 31;
    const int wm = wid >> 1;
    const int wn = wid & 1;
    const int b0 = blockIdx.x * 128;
    const int c0 = blockIdx.y * 64;

    float d[4][4][4];
    #pragma unroll
    for (int mi = 0; mi < 4; ++mi)
        #pragma unroll
        for (int nj = 0; nj < 4; ++nj)
            #pragma unroll
            for (int c = 0; c < 4; ++c) d[mi][nj][c] = 0.f;

    const int niters = N >> 6;
    const int lrow = tid >> 3;
    const int lseg = tid & 7;
    const int a_row = wm * 64 + (lane & 15);
    const int a_cb  = (lane >> 4) * 16;
    const int b_row = wn * 32 + (lane & 7) + ((lane >> 4) << 3);
    const int b_cb  = ((lane >> 3) & 1) * 16;

    auto issue_loads = [&](int it, int st) {
        const int k0 = it << 6;
        uint32_t sA = sb + st * 16384;
        uint32_t sB = sb + LSM_B_OFF + st * 8192;
        #pragma unroll
        for (int i = 0; i < 8; ++i) {
            int row = lrow + i * 16;
            uint32_t so = swz(row * 128 + lseg * 16);
            cp16(sA + so, preh + (size_t)(b0 + row) * N + k0 + lseg * 8);
        }
        #pragma unroll
        for (int i = 0; i < 4; ++i) {
            int c = tid + i * 128;      // 0..511
            int row = c >> 3, seg = c & 7;
            uint32_t so = swz(row * 128 + seg * 16);
            cp16(sB + so, Lat + (size_t)(c0 + row) * N + k0 + seg * 8);
        }
        CP_COMMIT();
    };

    issue_loads(0, 0);
    if (niters > 1) issue_loads(1, 1);

    int cur = 0;
    for (int it = 0; it < niters; ++it) {
        if (it == niters - 1) { CP_WAIT(0); } else { CP_WAIT(1); }
        __syncthreads();
        if (it + 2 < niters) {
            int nx = cur + 2; if (nx >= 3) nx -= 3;
            issue_loads(it + 2, nx);
        }

        uint32_t sA = sb + cur * 16384;
        uint32_t sB = sb + LSM_B_OFF + cur * 8192;
        #pragma unroll
        for (int ks = 0; ks < 4; ++ks) {
            uint32_t afr[4][4], bfr[2][4];
            #pragma unroll
            for (int mi = 0; mi < 4; ++mi)
                ldm_x4(afr[mi], sA + swz((a_row + mi * 16) * 128 + ks * 32 + a_cb));
            #pragma unroll
            for (int nj2 = 0; nj2 < 2; ++nj2)
                ldm_x4(bfr[nj2], sB + swz((b_row + nj2 * 16) * 128 + ks * 32 + b_cb));
            #pragma unroll
            for (int mi = 0; mi < 4; ++mi)
                #pragma unroll
                for (int nj = 0; nj < 4; ++nj)
                    mma16816(d[mi][nj], afr[mi], &bfr[nj >> 1][(nj & 1) * 2]);
        }
        cur = (cur == 2) ? 0 : cur + 1;
        if (it + 2 < niters) {} // keep structure
    }

    // epilogue: write h (f32) and hh (fp16)
    {
        const int g = lane >> 2, i = lane & 3;
        #pragma unroll
        for (int mi = 0; mi < 4; ++mi) {
            #pragma unroll
            for (int nj = 0; nj < 4; ++nj) {
                int c = c0 + wn * 32 + nj * 8 + 2 * i;
                int r = b0 + wm * 64 + mi * 16 + g;
                *(float2*)(h + (size_t)r * N + c) = make_float2(d[mi][nj][0], d[mi][nj][1]);
                *(__half2*)(hh + (size_t)r * N + c) = __floats2half2_rn(d[mi][nj][0], d[mi][nj][1]);
                *(float2*)(h + (size_t)(r + 8) * N + c) = make_float2(d[mi][nj][2], d[mi][nj][3]);
                *(__half2*)(hh + (size_t)(r + 8) * N + c) = __floats2half2_rn(d[mi][nj][2], d[mi][nj][3]);
            }
        }
    }
}

// ---------------- merged weight transpose (all 3 layers, one launch) ----------------
__global__ __launch_bounds__(256)
void wsplit_all_kernel(const float* __restrict__ Wi0, const float* __restrict__ Wi1,
                       const float* __restrict__ Wi2, __half* __restrict__ wth)
{
    int b = blockIdx.x;
    const float* Wi; __half* dst; int K, n, kc;
    if (b < 2048)      { Wi = Wi0; dst = wth;            K = 512; kc = b & 7; n = b >> 3; }
    else if (b < 2560) { b -= 2048; Wi = Wi1; dst = wth + 8388608;  K = 256; kc = b & 3; n = b >> 2; }
    else               { b -= 2560; Wi = Wi2; dst = wth + 10485760; K = 128; kc = b & 1; n = b >> 1; }
    const int k0 = kc * 64;

    __shared__ float tile[64][65];
    const float* src = Wi + ((size_t)n * K + k0) * SDIM;
    for (int i = threadIdx.x; i < 4096; i += 256) {
        int kk = i >> 6, s = i & 63;
        tile[kk][s] = src[kk * SDIM + s];
    }
    __syncthreads();
    for (int i = threadIdx.x; i < 4096; i += 256) {
        int s = i >> 6, kk = i & 63;
        dst[(size_t)n * SDIM * K + (size_t)s * K + k0 + kk] = __float2half(tile[kk][s]);
    }
}

// ---------------- La^T prep (all 3 layers, one launch; 336 blocks) ----------------
__global__ __launch_bounds__(256)
void latprep_kernel(const float* __restrict__ L0, const float* __restrict__ a0,
                    const float* __restrict__ L1, const float* __restrict__ a1,
                    const float* __restrict__ L2, const float* __restrict__ a2,
                    __half* __restrict__ lat)
{
    int b = blockIdx.x;
    const float* L; const float* a; __half* dst; int N;
    if (b < 256)      { L = L0; a = a0; dst = lat;         N = 256; }
    else if (b < 320) { b -= 256; L = L1; a = a1; dst = lat + 65536; N = 128; }
    else              { b -= 320; L = L2; a = a2; dst = lat + 81920; N = 64; }
    int e = b * 256 + threadIdx.x;
    int n = e / N, k = e - n * N;
    float v = 0.1f * L[(size_t)k * N + n] * a[n];
    if (k == n) v += a[n];
    dst[e] = __float2half(v);
}

// ---------------- x -> fp16 (vectorized, 4 elems/thread) ----------------
__global__ __launch_bounds__(256)
void xsplit_kernel(const float* __restrict__ x, __half* __restrict__ xh, int n4)
{
    int i = blockIdx.x * 256 + threadIdx.x;
    if (i >= n4) return;
    float4 v = ((const float4*)x)[i];
    ((__half2*)xh)[2 * i]     = __floats2half2_rn(v.x, v.y);
    ((__half2*)xh)[2 * i + 1] = __floats2half2_rn(v.z, v.w);
}

// ---------------- final projection ----------------
__global__ __launch_bounds__(256)
void out_kernel(const float* __restrict__ h, const float* __restrict__ Wout,
                const float* __restrict__ bout, float* __restrict__ y)
{
    int idx = blockIdx.x * blockDim.x + threadIdx.x;
    if (idx >= BATCH * OUTD) return;
    int b = idx / OUTD;
    int o = idx - b * OUTD;
    const float* hb = h + (size_t)b * 64;
    float s = bout[o];
    #pragma unroll
    for (int m = 0; m < 64; ++m)
        s += hb[m] * Wout[m * OUTD + o];
    y[idx] = s;
}

extern "C" void kernel_launch(void* const* d_in, const int* in_sizes, int n_in,
                              void* d_out, int out_size)
{
    (void)in_sizes; (void)n_in; (void)out_size;
    const float* x = (const float*)d_in[0];
    const float *Wi[3], *bi[3], *bl[3], *Wo[3], *bo[3], *Lm[3], *ad[3];
    for (int l = 0; l < 3; ++l) {
        int base = 1 + 7 * l;
        Wi[l] = (const float*)d_in[base + 0];
        bi[l] = (const float*)d_in[base + 1];
        bl[l] = (const float*)d_in[base + 2];
        Wo[l] = (const float*)d_in[base + 3];
        bo[l] = (const float*)d_in[base + 4];
        Lm[l] = (const float*)d_in[base + 5];
        ad[l] = (const float*)d_in[base + 6];
    }
    const float* Wout = (const float*)d_in[22];
    const float* bout = (const float*)d_in[23];

    __half *ah, *wth, *preh, *lat;
    float *h;
    cudaGetSymbolAddress((void**)&ah,   g_ah);
    cudaGetSymbolAddress((void**)&wth,  g_wth);
    cudaGetSymbolAddress((void**)&preh, g_preh);
    cudaGetSymbolAddress((void**)&lat,  g_lat);
    cudaGetSymbolAddress((void**)&h,    g_h);

    cudaFuncSetAttribute(liquid_mma_kernel, cudaFuncAttributeMaxDynamicSharedMemorySize, SM_TOTAL);
    cudaFuncSetAttribute(lat_mma_kernel, cudaFuncAttributeMaxDynamicSharedMemorySize, LSM_TOTAL);

    const int Ns[3] = {256, 128, 64};
    const int Ks[3] = {512, 256, 128};
    const size_t woff[3] = {0, 8388608, 10485760};
    const size_t loff[3] = {0, 65536, 81920};

    wsplit_all_kernel<<<2688, 256>>>(Wi[0], Wi[1], Wi[2], wth);
    latprep_kernel<<<336, 256>>>(Lm[0], ad[0], Lm[1], ad[1], Lm[2], ad[2], lat);
    xsplit_kernel<<<(BATCH * 512 / 4 + 255) / 256, 256>>>(x, ah, BATCH * 512 / 4);

    for (int l = 0; l < 3; ++l) {
        dim3 grid(BATCH / BM, (Ns[l] * SDIM) / BN);   // = Ns[l]/2
        liquid_mma_kernel<<<grid, 128, SM_TOTAL>>>(ah, wth + woff[l],
                                                   bi[l], bl[l], Wo[l], bo[l], preh,
                                                   Ks[l], Ns[l]);
        dim3 lgrid(BATCH / 128, Ns[l] / 64);
        lat_mma_kernel<<<lgrid, 128, LSM_TOTAL>>>(preh, lat + loff[l], h, ah, Ns[l]);
    }
    out_kernel<<<(BATCH * OUTD + 255) / 256, 256>>>(h, Wout, bout, (float*)d_out);
}